// round 9
// baseline (speedup 1.0000x reference)
#include <cuda_runtime.h>
#include <cuda_fp16.h>
#include <cstdint>

typedef uint32_t u32;

#define SQRTD_F 11.313708498984761f

// shared memory byte offsets (fragment-packed tiles)
#define SM_AH   0          // A hi  [8 mg][8 ks][32 lane] uint4 : 32768 B
#define SM_AL   32768      // A lo  : 32768 B
#define SM_BF   65536      // B fwd [16 ng][8 ks][32 lane] uint4 {bh0,bh1,bl0,bl1} : 65536 B
#define SM_BB   131072     // B bwd : 65536 B
#define SM_MISC 196608
#define SMEM_BYTES 200448

static __device__ __forceinline__ u32 hpack(__half a, __half b) {
    return (u32)__half_as_ushort(a) | ((u32)__half_as_ushort(b) << 16);
}

static __device__ __forceinline__ void mma16(float c[4], u32 a0, u32 a1, u32 a2, u32 a3,
                                             u32 b0, u32 b1) {
    asm volatile(
        "mma.sync.aligned.m16n8k16.row.col.f32.f16.f16.f32 "
        "{%0,%1,%2,%3},{%4,%5,%6,%7},{%8,%9},{%0,%1,%2,%3};"
        : "+f"(c[0]), "+f"(c[1]), "+f"(c[2]), "+f"(c[3])
        : "r"(a0), "r"(a1), "r"(a2), "r"(a3), "r"(b0), "r"(b1));
}

// K=128 GEMM over a 32(M) x 32(N) warp tile. Pure LDS.128 fragment loads.
// NP=3: hh+hl+lh ; NP=2: hh+hl (A_lo unused).
template<int NP>
static __device__ __forceinline__ void chain(const uint4* __restrict__ sAh,
                                             const uint4* __restrict__ sAl,
                                             const uint4* __restrict__ sB,
                                             float acc[2][4][4],
                                             int lane, int mg0, int ng0) {
    #pragma unroll 1
    for (int ks = 0; ks < 8; ks++) {
        uint4 B[4];
        #pragma unroll
        for (int nt = 0; nt < 4; nt++)
            B[nt] = sB[((ng0 + nt) * 8 + ks) * 32 + lane];
        uint4 Ah[2];
        #pragma unroll
        for (int mt = 0; mt < 2; mt++)
            Ah[mt] = sAh[((mg0 + mt) * 8 + ks) * 32 + lane];
        uint4 Al[2];
        if (NP == 3) {
            #pragma unroll
            for (int mt = 0; mt < 2; mt++)
                Al[mt] = sAl[((mg0 + mt) * 8 + ks) * 32 + lane];
        }
        #pragma unroll
        for (int mt = 0; mt < 2; mt++)
            #pragma unroll
            for (int nt = 0; nt < 4; nt++)
                mma16(acc[mt][nt], Ah[mt].x, Ah[mt].y, Ah[mt].z, Ah[mt].w,
                      B[nt].x, B[nt].y);
        #pragma unroll
        for (int mt = 0; mt < 2; mt++)
            #pragma unroll
            for (int nt = 0; nt < 4; nt++)
                mma16(acc[mt][nt], Ah[mt].x, Ah[mt].y, Ah[mt].z, Ah[mt].w,
                      B[nt].z, B[nt].w);
        if (NP == 3) {
            #pragma unroll
            for (int mt = 0; mt < 2; mt++)
                #pragma unroll
                for (int nt = 0; nt < 4; nt++)
                    mma16(acc[mt][nt], Al[mt].x, Al[mt].y, Al[mt].z, Al[mt].w,
                          B[nt].x, B[nt].y);
        }
    }
}

__global__ __launch_bounds__(512, 1)
void tq_fused(const float* __restrict__ x, const float* __restrict__ Pi,
              const float* __restrict__ cbk, float* __restrict__ out) {
    extern __shared__ char sm[];
    u32*   aH = (u32*)(sm + SM_AH);
    u32*   aL = (u32*)(sm + SM_AL);
    u32*   bF = (u32*)(sm + SM_BF);
    __half* s_csdh = (__half*)(sm + SM_MISC);          // 16 fp16
    float*  s_mid   = (float*)(sm + SM_MISC + 64);     // 15 f32
    float*  s_part  = (float*)(sm + SM_MISC + 192);    // 512 f32
    float*  s_scale = (float*)(sm + SM_MISC + 2240);   // 128 f32 (sqrt_d/norm)
    float*  s_nh    = (float*)(sm + SM_MISC + 2752);   // 128 f32

    const int tid = threadIdx.x;
    const int wid = tid >> 5, lane = tid & 31;
    const int g = lane >> 2, t = lane & 3;
    const int mg0 = (wid >> 2) * 2;        // M 16-row-group base (0..7)
    const int ng0 = (wid & 3) * 4;         // N 8-row-group base (0..15)
    const int mrow0 = mg0 * 16, ncol0 = ng0 * 8;
    const int tok0 = blockIdx.x << 7;

    // ---- load x (4 threads/token): stage packed A hi/lo from RAW x ----
    const int r = tid >> 2, c0 = (tid & 3) * 32;
    {
        const float4* xr = (const float4*)(x + (size_t)(tok0 + r) * 128 + c0);
        float v[32];
        float ss = 0.f;
        #pragma unroll
        for (int e = 0; e < 8; e++) {
            float4 p = xr[e];
            v[4 * e] = p.x; v[4 * e + 1] = p.y; v[4 * e + 2] = p.z; v[4 * e + 3] = p.w;
            ss += p.x * p.x + p.y * p.y + p.z * p.z + p.w * p.w;
        }
        s_part[tid] = ss;
        const int rg = r >> 4, r16 = r & 15, ga = r16 & 7, a01 = r16 >> 3;
        #pragma unroll
        for (int e = 0; e < 16; e++) {
            const int p = (c0 >> 1) + e;
            const int ks = p >> 3, tt = p & 3, hk = (p >> 2) & 1;
            const int word = ((rg * 8 + ks) * 32 + ga * 4 + tt) * 4 + a01 + 2 * hk;
            float u0 = v[2 * e], u1 = v[2 * e + 1];
            __half h0 = __float2half_rn(u0), h1 = __float2half_rn(u1);
            aH[word] = hpack(h0, h1);
            aL[word] = hpack(__float2half_rn(u0 - __half2float(h0)),
                             __float2half_rn(u1 - __half2float(h1)));
        }
    }

    // ---- load Pi once (coalesced rows); stage Bf (row-major) and Bb (transposed) ----
    {
        const int n = r, kh = c0;                       // same mapping as x
        const float4* pr = (const float4*)(Pi + n * 128 + kh);
        const int ng = n >> 3, gb = n & 7;
        const int pj = n >> 1, jh = n & 1;              // Bb k-pair of row j=n
        const int ksb = pj >> 3, tb = pj & 3, hkb = (pj >> 2) & 1;
        #pragma unroll
        for (int e = 0; e < 8; e++) {
            float4 pv = pr[e];
            // Bf: two k-pairs
            {
                const int p0 = (kh >> 1) + 2 * e;
                __half hx = __float2half_rn(pv.x), hy = __float2half_rn(pv.y);
                __half hz = __float2half_rn(pv.z), hw = __float2half_rn(pv.w);
                int ks = p0 >> 3, tt = p0 & 3, hk = (p0 >> 2) & 1;
                int w0 = ((ng * 8 + ks) * 32 + gb * 4 + tt) * 4 + hk;
                bF[w0]     = hpack(hx, hy);
                bF[w0 + 2] = hpack(__float2half_rn(pv.x - __half2float(hx)),
                                   __float2half_rn(pv.y - __half2float(hy)));
                const int p1 = p0 + 1;
                ks = p1 >> 3; tt = p1 & 3; hk = (p1 >> 2) & 1;
                int w1 = ((ng * 8 + ks) * 32 + gb * 4 + tt) * 4 + hk;
                bF[w1]     = hpack(hz, hw);
                bF[w1 + 2] = hpack(__float2half_rn(pv.z - __half2float(hz)),
                                   __float2half_rn(pv.w - __half2float(hw)));
            }
            // Bb: transpose -> Bb[i][j=n], 4 scalars
            float pe[4] = {pv.x, pv.y, pv.z, pv.w};
            #pragma unroll
            for (int c = 0; c < 4; c++) {
                const int i = kh + 4 * e + c;
                const int ngb = i >> 3, gg = i & 7;
                const int word = ((ngb * 8 + ksb) * 32 + gg * 4 + tb) * 4 + hkb;
                __half hv = __float2half_rn(pe[c]);
                *(__half*)(sm + SM_BB + word * 4 + jh * 2) = hv;
                *(__half*)(sm + SM_BB + (word + 2) * 4 + jh * 2) =
                    __float2half_rn(pe[c] - __half2float(hv));
            }
        }
    }

    if (tid < 16) {
        float c = cbk[tid];
        s_csdh[tid] = __float2half_rn(__fdiv_rn(c, SQRTD_F));
        if (tid < 15) s_mid[tid] = (c + cbk[tid + 1]) * 0.5f;
    }
    __syncthreads();

    // ---- norms (overlap with fwd chain of other warps; visible after sync2) ----
    if (tid < 128) {
        float s = s_part[4 * tid] + s_part[4 * tid + 1]
                + s_part[4 * tid + 2] + s_part[4 * tid + 3];
        float n = __fsqrt_rn(s);
        float cn = fmaxf(n, 1e-8f);
        s_scale[tid] = __fdiv_rn(SQRTD_F, cn);
        s_nh[tid] = __half2float(__float2half_rn(n));
    }

    float acc[2][4][4];
    #pragma unroll
    for (int i = 0; i < 2; i++)
        #pragma unroll
        for (int j = 0; j < 4; j++)
            #pragma unroll
            for (int k = 0; k < 4; k++) acc[i][j][k] = 0.f;

    // ---- forward: y_raw = x @ Pi^T  (3-product hi/lo fp16) ----
    chain<3>((const uint4*)aH, (const uint4*)aL, (const uint4*)(sm + SM_BF),
             acc, lane, mg0, ng0);
    __syncthreads();

    // ---- quantize: y = y_raw * (sqrt_d/norm); write fp16 csd into packed A_hi ----
    {
        float mids[15];
        #pragma unroll
        for (int l = 0; l < 15; l++) mids[l] = s_mid[l];
        #pragma unroll
        for (int mt = 0; mt < 2; mt++) {
            const float sc0 = s_scale[mrow0 + mt * 16 + g];
            const float sc1 = s_scale[mrow0 + mt * 16 + g + 8];
            #pragma unroll
            for (int nt = 0; nt < 4; nt++) {
                const int p = (ncol0 >> 1) + nt * 4 + t;
                const int ks = p >> 3, tc = p & 3, hk = (p >> 2) & 1;
                const int wbase = (((mg0 + mt) * 8 + ks) * 32 + g * 4 + tc) * 4 + 2 * hk;
                #pragma unroll
                for (int rr = 0; rr < 4; rr++) {
                    float y = acc[mt][nt][rr] * ((rr >> 1) ? sc1 : sc0);
                    int idx = 0;
                    #pragma unroll
                    for (int l = 0; l < 15; l++) idx += (y > mids[l]);
                    const int word = wbase + (rr >> 1);
                    *(__half*)(sm + SM_AH + word * 4 + (rr & 1) * 2) = s_csdh[idx];
                    acc[mt][nt][rr] = 0.f;
                }
            }
        }
    }
    __syncthreads();

    // ---- backward: z = a_hat @ Pi  (2-product: a_hi * (Pi_hi + Pi_lo)) ----
    chain<2>((const uint4*)aH, (const uint4*)aL, (const uint4*)(sm + SM_BB),
             acc, lane, mg0, ng0);

    // ---- epilogue: scale by fp16-roundtripped norm, store float2 ----
    #pragma unroll
    for (int mt = 0; mt < 2; mt++) {
        #pragma unroll
        for (int nt = 0; nt < 4; nt++) {
            int row0 = mrow0 + mt * 16 + g;
            int col  = ncol0 + nt * 8 + 2 * t;
            float nh0 = s_nh[row0];
            float nh1 = s_nh[row0 + 8];
            *(float2*)(out + (size_t)(tok0 + row0) * 128 + col) =
                make_float2(acc[mt][nt][0] * nh0, acc[mt][nt][1] * nh0);
            *(float2*)(out + (size_t)(tok0 + row0 + 8) * 128 + col) =
                make_float2(acc[mt][nt][2] * nh1, acc[mt][nt][3] * nh1);
        }
    }
}

extern "C" void kernel_launch(void* const* d_in, const int* in_sizes, int n_in,
                              void* d_out, int out_size) {
    const float* x   = (const float*)d_in[0];
    const float* Pi  = (const float*)d_in[1];
    const float* cbk = (const float*)d_in[2];
    float* out = (float*)d_out;

    int ntok = in_sizes[0] / 128;
    int blocks = ntok / 128;

    cudaFuncSetAttribute(tq_fused, cudaFuncAttributeMaxDynamicSharedMemorySize, SMEM_BYTES);
    tq_fused<<<blocks, 512, SMEM_BYTES>>>(x, Pi, cbk, out);
}

// round 10
// speedup vs baseline: 1.1424x; 1.1424x over previous
#include <cuda_runtime.h>
#include <cuda_fp16.h>
#include <cstdint>

typedef uint32_t u32;

#define SQRTD_F 11.313708498984761f

// uint4 tiles: 128 rows x 36 uint4 (32 data + 4 pad) = 73728 B each
#define SM_A    0
#define SM_BF   73728
#define SM_BB   147456
#define SM_MISC 221184
#define SMEM_BYTES 224448

// word index (uint4 units): XOR swizzle keeps chain loads AND staging stores conflict-free
static __device__ __forceinline__ int W4(int row, int ks, int t) {
    return row * 36 + ks * 4 + (t ^ ((ks >> 1) & 3));
}

static __device__ __forceinline__ u32 hpack(__half a, __half b) {
    return (u32)__half_as_ushort(a) | ((u32)__half_as_ushort(b) << 16);
}

static __device__ __forceinline__ void mma16(float c[4], u32 a0, u32 a1, u32 a2, u32 a3,
                                             u32 b0, u32 b1) {
    asm volatile(
        "mma.sync.aligned.m16n8k16.row.col.f32.f16.f16.f32 "
        "{%0,%1,%2,%3},{%4,%5,%6,%7},{%8,%9},{%0,%1,%2,%3};"
        : "+f"(c[0]), "+f"(c[1]), "+f"(c[2]), "+f"(c[3])
        : "r"(a0), "r"(a1), "r"(a2), "r"(a3), "r"(b0), "r"(b1));
}

// pack 32 fp32 (16 k-pairs) of one row-quarter into the uint4 tile (2 k-steps)
static __device__ __forceinline__ void stage_pack(uint4* tile, const float* v,
                                                  int row, int q) {
    #pragma unroll
    for (int s = 0; s < 2; s++) {
        const int ks = 2 * q + s;
        #pragma unroll
        for (int t = 0; t < 4; t++) {
            const int l0 = 8 * s + t, l1 = l0 + 4;
            float v00 = v[2 * l0], v01 = v[2 * l0 + 1];
            float v10 = v[2 * l1], v11 = v[2 * l1 + 1];
            __half h00 = __float2half_rn(v00), h01 = __float2half_rn(v01);
            __half h10 = __float2half_rn(v10), h11 = __float2half_rn(v11);
            uint4 val;
            val.x = hpack(h00, h01);
            val.y = hpack(h10, h11);
            val.z = hpack(__float2half_rn(v00 - __half2float(h00)),
                          __float2half_rn(v01 - __half2float(h01)));
            val.w = hpack(__float2half_rn(v10 - __half2float(h10)),
                          __float2half_rn(v11 - __half2float(h11)));
            tile[W4(row, ks, t)] = val;
        }
    }
}

// K=128 GEMM, 32(M) x 32(N) warp tile, uint4 fragment loads.
// NP=3: hh+hl+lh ; NP=2: hh+hl.
template<int NP>
static __device__ __forceinline__ void chain(const uint4* __restrict__ sA,
                                             const uint4* __restrict__ sB,
                                             float acc[2][4][4],
                                             int g, int t, int mrow0, int ncol0) {
    #pragma unroll 2
    for (int ks = 0; ks < 8; ks++) {
        const int tx = t ^ ((ks >> 1) & 3);
        const int kbase = ks * 4 + tx;
        uint4 B[4];
        #pragma unroll
        for (int nt = 0; nt < 4; nt++)
            B[nt] = sB[(ncol0 + nt * 8 + g) * 36 + kbase];
        uint4 A0[2], A1[2];
        #pragma unroll
        for (int mt = 0; mt < 2; mt++) {
            A0[mt] = sA[(mrow0 + mt * 16 + g) * 36 + kbase];
            A1[mt] = sA[(mrow0 + mt * 16 + g + 8) * 36 + kbase];
        }
        #pragma unroll
        for (int mt = 0; mt < 2; mt++)
            #pragma unroll
            for (int nt = 0; nt < 4; nt++)
                mma16(acc[mt][nt], A0[mt].x, A1[mt].x, A0[mt].y, A1[mt].y,
                      B[nt].x, B[nt].y);
        #pragma unroll
        for (int mt = 0; mt < 2; mt++)
            #pragma unroll
            for (int nt = 0; nt < 4; nt++)
                mma16(acc[mt][nt], A0[mt].x, A1[mt].x, A0[mt].y, A1[mt].y,
                      B[nt].z, B[nt].w);
        if (NP == 3) {
            #pragma unroll
            for (int mt = 0; mt < 2; mt++)
                #pragma unroll
                for (int nt = 0; nt < 4; nt++)
                    mma16(acc[mt][nt], A0[mt].z, A1[mt].z, A0[mt].w, A1[mt].w,
                          B[nt].x, B[nt].y);
        }
    }
}

__global__ __launch_bounds__(512, 1)
void tq_fused(const float* __restrict__ x, const float* __restrict__ Pi,
              const float* __restrict__ cbk, float* __restrict__ out) {
    extern __shared__ char sm[];
    uint4* sA4  = (uint4*)(sm + SM_A);
    uint4* sBf4 = (uint4*)(sm + SM_BF);
    uint4* sBb4 = (uint4*)(sm + SM_BB);
    __half* s_csdh  = (__half*)(sm + SM_MISC);          // 16 fp16
    float*  s_mid   = (float*)(sm + SM_MISC + 64);      // 15 f32
    float*  s_part  = (float*)(sm + SM_MISC + 192);     // 512 f32
    float*  s_scale = (float*)(sm + SM_MISC + 2240);    // 128 f32
    float*  s_nh    = (float*)(sm + SM_MISC + 2752);    // 128 f32

    const int tid = threadIdx.x;
    const int wid = tid >> 5, lane = tid & 31;
    const int g = lane >> 2, t = lane & 3;
    const int mrow0 = (wid >> 2) * 32;
    const int ncol0 = (wid & 3) * 32;
    const int tok0 = blockIdx.x << 7;

    const int r = tid >> 2, q = tid & 3, c0 = q * 32;

    // ---- load x quarter-row; stage packed A (raw x); partial sum of squares ----
    {
        const float4* xr = (const float4*)(x + (size_t)(tok0 + r) * 128 + c0);
        float v[32];
        float ss = 0.f;
        #pragma unroll
        for (int e = 0; e < 8; e++) {
            float4 p = xr[e];
            v[4 * e] = p.x; v[4 * e + 1] = p.y; v[4 * e + 2] = p.z; v[4 * e + 3] = p.w;
            ss += p.x * p.x + p.y * p.y + p.z * p.z + p.w * p.w;
        }
        s_part[tid] = ss;
        stage_pack(sA4, v, r, q);
    }
    // ---- stage Bf = Pi row-major (coalesced row reads) ----
    {
        const float4* pr = (const float4*)(Pi + r * 128 + c0);
        float v[32];
        #pragma unroll
        for (int e = 0; e < 8; e++) {
            float4 p = pr[e];
            v[4 * e] = p.x; v[4 * e + 1] = p.y; v[4 * e + 2] = p.z; v[4 * e + 3] = p.w;
        }
        stage_pack(sBf4, v, r, q);
    }
    // ---- stage Bb[i=r][j] = Pi[j][r] (strided column reads, then clean STS.128) ----
    {
        float v[32];
        #pragma unroll 8
        for (int jj = 0; jj < 32; jj++)
            v[jj] = Pi[(size_t)(c0 + jj) * 128 + r];
        stage_pack(sBb4, v, r, q);
    }

    if (tid < 16) {
        float c = cbk[tid];
        s_csdh[tid] = __float2half_rn(__fdiv_rn(c, SQRTD_F));
        if (tid < 15) s_mid[tid] = (c + cbk[tid + 1]) * 0.5f;
    }
    __syncthreads();

    // ---- norms (first 4 warps; overlaps other warps' fwd chain start) ----
    if (tid < 128) {
        float s = s_part[4 * tid] + s_part[4 * tid + 1]
                + s_part[4 * tid + 2] + s_part[4 * tid + 3];
        float n = __fsqrt_rn(s);
        float cn = fmaxf(n, 1e-8f);
        s_scale[tid] = __fdiv_rn(SQRTD_F, cn);
        s_nh[tid] = __half2float(__float2half_rn(n));
    }

    float acc[2][4][4];
    #pragma unroll
    for (int i = 0; i < 2; i++)
        #pragma unroll
        for (int j = 0; j < 4; j++)
            #pragma unroll
            for (int k = 0; k < 4; k++) acc[i][j][k] = 0.f;

    // ---- forward: y_raw = x @ Pi^T  (3-product hi/lo fp16) ----
    chain<3>(sA4, sBf4, acc, g, t, mrow0, ncol0);
    __syncthreads();

    // ---- quantize: y = y_raw*(sqrt_d/norm); write packed fp16 csd pairs into A hi ----
    {
        float mids[15];
        #pragma unroll
        for (int l = 0; l < 15; l++) mids[l] = s_mid[l];
        u32* aW = (u32*)(sm + SM_A);
        #pragma unroll
        for (int mt = 0; mt < 2; mt++) {
            const int row0 = mrow0 + mt * 16 + g;
            const float sc0 = s_scale[row0];
            const float sc1 = s_scale[row0 + 8];
            #pragma unroll
            for (int nt = 0; nt < 4; nt++) {
                const int p = (ncol0 >> 1) + nt * 4 + t;       // k-pair index
                const int ks = p >> 3, tt = p & 3, hh = (p >> 2) & 1;
                const int widx = W4(0, ks, tt) * 4 + hh;       // row added below
                int i0, i1;
                {
                    float y0 = acc[mt][nt][0] * sc0, y1 = acc[mt][nt][1] * sc0;
                    i0 = 0; i1 = 0;
                    #pragma unroll
                    for (int l = 0; l < 15; l++) { i0 += (y0 > mids[l]); i1 += (y1 > mids[l]); }
                    aW[row0 * 144 + widx] = hpack(s_csdh[i0], s_csdh[i1]);
                }
                {
                    float y0 = acc[mt][nt][2] * sc1, y1 = acc[mt][nt][3] * sc1;
                    i0 = 0; i1 = 0;
                    #pragma unroll
                    for (int l = 0; l < 15; l++) { i0 += (y0 > mids[l]); i1 += (y1 > mids[l]); }
                    aW[(row0 + 8) * 144 + widx] = hpack(s_csdh[i0], s_csdh[i1]);
                }
                acc[mt][nt][0] = 0.f; acc[mt][nt][1] = 0.f;
                acc[mt][nt][2] = 0.f; acc[mt][nt][3] = 0.f;
            }
        }
    }
    __syncthreads();

    // ---- backward: z = a_hat @ Pi  (2-product: a_hi * (Pi_hi + Pi_lo)) ----
    chain<2>(sA4, sBb4, acc, g, t, mrow0, ncol0);

    // ---- epilogue: scale by fp16-roundtripped norm, store float2 ----
    #pragma unroll
    for (int mt = 0; mt < 2; mt++) {
        #pragma unroll
        for (int nt = 0; nt < 4; nt++) {
            int row0 = mrow0 + mt * 16 + g;
            int col  = ncol0 + nt * 8 + 2 * t;
            float nh0 = s_nh[row0];
            float nh1 = s_nh[row0 + 8];
            *(float2*)(out + (size_t)(tok0 + row0) * 128 + col) =
                make_float2(acc[mt][nt][0] * nh0, acc[mt][nt][1] * nh0);
            *(float2*)(out + (size_t)(tok0 + row0 + 8) * 128 + col) =
                make_float2(acc[mt][nt][2] * nh1, acc[mt][nt][3] * nh1);
        }
    }
}

extern "C" void kernel_launch(void* const* d_in, const int* in_sizes, int n_in,
                              void* d_out, int out_size) {
    const float* x   = (const float*)d_in[0];
    const float* Pi  = (const float*)d_in[1];
    const float* cbk = (const float*)d_in[2];
    float* out = (float*)d_out;

    int ntok = in_sizes[0] / 128;
    int blocks = ntok / 128;

    cudaFuncSetAttribute(tq_fused, cudaFuncAttributeMaxDynamicSharedMemorySize, SMEM_BYTES);
    tq_fused<<<blocks, 512, SMEM_BYTES>>>(x, Pi, cbk, out);
}

// round 11
// speedup vs baseline: 1.1942x; 1.0453x over previous
#include <cuda_runtime.h>
#include <cuda_fp16.h>
#include <cstdint>

typedef uint32_t u32;

#define SQRTD_F 11.313708498984761f
#define PR 68          // u32 row stride -> (4g+t) conflict-free fragment loads
#define PRB (PR * 4)

// shared memory byte offsets
#define SM_AH   0          // A hi : 64 x 68 u32 = 17408 B
#define SM_AL   17408      // A lo : 17408 B
#define SM_BH   34816      // B hi : 128 x 68 u32 = 34816 B
#define SM_BL   69632      // B lo : 34816 B
#define SM_MISC 104448
#define SMEM_BYTES 106496

static __device__ __forceinline__ u32 hpack(__half a, __half b) {
    return (u32)__half_as_ushort(a) | ((u32)__half_as_ushort(b) << 16);
}

static __device__ __forceinline__ void mma16(float c[4], u32 a0, u32 a1, u32 a2, u32 a3,
                                             u32 b0, u32 b1) {
    asm volatile(
        "mma.sync.aligned.m16n8k16.row.col.f32.f16.f16.f32 "
        "{%0,%1,%2,%3},{%4,%5,%6,%7},{%8,%9},{%0,%1,%2,%3};"
        : "+f"(c[0]), "+f"(c[1]), "+f"(c[2]), "+f"(c[3])
        : "r"(a0), "r"(a1), "r"(a2), "r"(a3), "r"(b0), "r"(b1));
}

// K=128 GEMM over a 32(M) x 32(N) warp tile using packed-fp16 hi/lo arrays.
// NP=3: hh+hl+lh.  NP=2: hh+hl (A_lo unused).
template<int NP>
static __device__ __forceinline__ void chain(const u32* __restrict__ sAh,
                                             const u32* __restrict__ sAl,
                                             const u32* __restrict__ sBh,
                                             const u32* __restrict__ sBl,
                                             float acc[2][4][4],
                                             int g, int t, int mrow0, int ncol0) {
    #pragma unroll 1
    for (int ks = 0; ks < 8; ks++) {
        const int kp = ks * 8;
        u32 bh[4][2], bl[4][2];
        #pragma unroll
        for (int nt = 0; nt < 4; nt++) {
            const int off = (ncol0 + nt * 8 + g) * PR + kp + t;
            bh[nt][0] = sBh[off];     bh[nt][1] = sBh[off + 4];
            bl[nt][0] = sBl[off];     bl[nt][1] = sBl[off + 4];
        }
        u32 ah[2][4], al[2][4];
        #pragma unroll
        for (int mt = 0; mt < 2; mt++) {
            const int off = (mrow0 + mt * 16 + g) * PR + kp + t;
            ah[mt][0] = sAh[off];            ah[mt][1] = sAh[off + 8 * PR];
            ah[mt][2] = sAh[off + 4];        ah[mt][3] = sAh[off + 8 * PR + 4];
            if (NP == 3) {
                al[mt][0] = sAl[off];        al[mt][1] = sAl[off + 8 * PR];
                al[mt][2] = sAl[off + 4];    al[mt][3] = sAl[off + 8 * PR + 4];
            }
        }
        #pragma unroll
        for (int mt = 0; mt < 2; mt++)
            #pragma unroll
            for (int nt = 0; nt < 4; nt++)
                mma16(acc[mt][nt], ah[mt][0], ah[mt][1], ah[mt][2], ah[mt][3],
                      bh[nt][0], bh[nt][1]);
        #pragma unroll
        for (int mt = 0; mt < 2; mt++)
            #pragma unroll
            for (int nt = 0; nt < 4; nt++)
                mma16(acc[mt][nt], ah[mt][0], ah[mt][1], ah[mt][2], ah[mt][3],
                      bl[nt][0], bl[nt][1]);
        if (NP == 3) {
            #pragma unroll
            for (int mt = 0; mt < 2; mt++)
                #pragma unroll
                for (int nt = 0; nt < 4; nt++)
                    mma16(acc[mt][nt], al[mt][0], al[mt][1], al[mt][2], al[mt][3],
                          bh[nt][0], bh[nt][1]);
        }
    }
}

__global__ __launch_bounds__(256, 2)
void tq_fused(const float* __restrict__ x, const float* __restrict__ Pi,
              const float* __restrict__ cbk, float* __restrict__ out) {
    extern __shared__ char sm[];
    u32* sAh = (u32*)(sm + SM_AH);
    u32* sAl = (u32*)(sm + SM_AL);
    u32* sBh = (u32*)(sm + SM_BH);
    u32* sBl = (u32*)(sm + SM_BL);
    __half* s_csdh  = (__half*)(sm + SM_MISC);          // 16 fp16
    float*  s_mid   = (float*)(sm + SM_MISC + 64);      // 15 f32
    float*  s_part  = (float*)(sm + SM_MISC + 192);     // 256 f32
    float*  s_scale = (float*)(sm + SM_MISC + 1216);    // 64 f32 (sqrt_d/norm)
    float*  s_nh    = (float*)(sm + SM_MISC + 1472);    // 64 f32

    const int tid = threadIdx.x;
    const int wid = tid >> 5, lane = tid & 31;
    const int g = lane >> 2, t = lane & 3;
    const int mrow0 = (wid >> 2) * 32;    // 2 M groups (rows 0..63)
    const int ncol0 = (wid & 3) * 32;     // 4 N groups (cols 0..127)
    const int tok0 = blockIdx.x << 6;     // 64 tokens / CTA

    // ---- stage Bf[n][kpair] = fp16 hi/lo of Pi[n][k] (coalesced row reads) ----
    const int bn = tid >> 1, bkh = (tid & 1) * 64;
    {
        const float4* pr = (const float4*)(Pi + bn * 128 + bkh);
        #pragma unroll
        for (int e = 0; e < 16; e++) {
            float4 p = pr[e];
            __half hx = __float2half_rn(p.x), hy = __float2half_rn(p.y);
            __half hz = __float2half_rn(p.z), hw = __float2half_rn(p.w);
            int idx = bn * PR + (bkh >> 1) + 2 * e;
            sBh[idx]     = hpack(hx, hy);
            sBh[idx + 1] = hpack(hz, hw);
            sBl[idx]     = hpack(__float2half_rn(p.x - __half2float(hx)),
                                 __float2half_rn(p.y - __half2float(hy)));
            sBl[idx + 1] = hpack(__float2half_rn(p.z - __half2float(hz)),
                                 __float2half_rn(p.w - __half2float(hw)));
        }
    }

    // ---- load x (4 threads/token); stage packed A hi/lo (raw x); partial SS ----
    const int token = tid >> 2, c0 = (tid & 3) * 32;
    {
        const float4* xr = (const float4*)(x + (size_t)(tok0 + token) * 128 + c0);
        float v[32];
        float ss = 0.f;
        #pragma unroll
        for (int e = 0; e < 8; e++) {
            float4 p = xr[e];
            v[4 * e] = p.x; v[4 * e + 1] = p.y; v[4 * e + 2] = p.z; v[4 * e + 3] = p.w;
            ss += p.x * p.x + p.y * p.y + p.z * p.z + p.w * p.w;
        }
        s_part[tid] = ss;
        #pragma unroll
        for (int e = 0; e < 16; e++) {
            float u0 = v[2 * e], u1 = v[2 * e + 1];
            __half h0 = __float2half_rn(u0), h1 = __float2half_rn(u1);
            int idx = token * PR + (c0 >> 1) + e;
            sAh[idx] = hpack(h0, h1);
            sAl[idx] = hpack(__float2half_rn(u0 - __half2float(h0)),
                             __float2half_rn(u1 - __half2float(h1)));
        }
    }
    if (tid < 16) {
        float c = cbk[tid];
        s_csdh[tid] = __float2half_rn(__fdiv_rn(c, SQRTD_F));
        if (tid < 15) s_mid[tid] = (c + cbk[tid + 1]) * 0.5f;
    }
    __syncthreads();

    // ---- norms (warps 0-1; other warps start the fwd chain meanwhile) ----
    if (tid < 64) {
        float s = s_part[4 * tid] + s_part[4 * tid + 1]
                + s_part[4 * tid + 2] + s_part[4 * tid + 3];
        float n = __fsqrt_rn(s);
        float cn = fmaxf(n, 1e-8f);
        s_scale[tid] = __fdiv_rn(SQRTD_F, cn);
        s_nh[tid] = __half2float(__float2half_rn(n));
    }

    float acc[2][4][4];
    #pragma unroll
    for (int i = 0; i < 2; i++)
        #pragma unroll
        for (int j = 0; j < 4; j++)
            #pragma unroll
            for (int k = 0; k < 4; k++) acc[i][j][k] = 0.f;

    // ---- forward: y_raw = x @ Pi^T  (3-product hi/lo fp16) ----
    chain<3>(sAh, sAl, sBh, sBl, acc, g, t, mrow0, ncol0);
    __syncthreads();   // everyone done reading A and B

    // ---- restage B with PiT columns (LDGs early to overlap quantize) ----
    {
        const int i = tid >> 1, jh = (tid & 1) * 64;
        #pragma unroll 1
        for (int b = 0; b < 2; b++) {
            float vc[32];
            #pragma unroll
            for (int p = 0; p < 32; p++)
                vc[p] = Pi[(size_t)(jh + b * 32 + p) * 128 + i];
            #pragma unroll
            for (int p = 0; p < 16; p++) {
                float v0 = vc[2 * p], v1 = vc[2 * p + 1];
                __half h0 = __float2half_rn(v0), h1 = __float2half_rn(v1);
                int idx = i * PR + ((jh + b * 32) >> 1) + p;
                sBh[idx] = hpack(h0, h1);
                sBl[idx] = hpack(__float2half_rn(v0 - __half2float(h0)),
                                 __float2half_rn(v1 - __half2float(h1)));
            }
        }
    }

    // ---- quantize: y = y_raw*(sqrt_d/norm); write fp16 csd into packed A_hi ----
    {
        float mids[15];
        #pragma unroll
        for (int l = 0; l < 15; l++) mids[l] = s_mid[l];
        #pragma unroll
        for (int mt = 0; mt < 2; mt++) {
            const float sc0 = s_scale[mrow0 + mt * 16 + g];
            const float sc1 = s_scale[mrow0 + mt * 16 + g + 8];
            #pragma unroll
            for (int nt = 0; nt < 4; nt++) {
                #pragma unroll
                for (int rr = 0; rr < 4; rr++) {
                    float y = acc[mt][nt][rr] * ((rr >> 1) ? sc1 : sc0);
                    int idx = 0;
                    #pragma unroll
                    for (int l = 0; l < 15; l++) idx += (y > mids[l]);
                    int row = mrow0 + mt * 16 + g + ((rr >> 1) << 3);
                    int col = ncol0 + nt * 8 + 2 * t + (rr & 1);
                    *(__half*)(sm + SM_AH + row * PRB + col * 2) = s_csdh[idx];
                    acc[mt][nt][rr] = 0.f;
                }
            }
        }
    }
    __syncthreads();

    // ---- backward: z = a_hat @ Pi  (2-product: a_hi * (PiT_hi + PiT_lo)) ----
    chain<2>(sAh, sAl, sBh, sBl, acc, g, t, mrow0, ncol0);

    // ---- epilogue: scale by fp16-roundtripped norm, store float2 ----
    #pragma unroll
    for (int mt = 0; mt < 2; mt++) {
        #pragma unroll
        for (int nt = 0; nt < 4; nt++) {
            int row0 = mrow0 + mt * 16 + g;
            int col  = ncol0 + nt * 8 + 2 * t;
            float nh0 = s_nh[row0];
            float nh1 = s_nh[row0 + 8];
            *(float2*)(out + (size_t)(tok0 + row0) * 128 + col) =
                make_float2(acc[mt][nt][0] * nh0, acc[mt][nt][1] * nh0);
            *(float2*)(out + (size_t)(tok0 + row0 + 8) * 128 + col) =
                make_float2(acc[mt][nt][2] * nh1, acc[mt][nt][3] * nh1);
        }
    }
}

extern "C" void kernel_launch(void* const* d_in, const int* in_sizes, int n_in,
                              void* d_out, int out_size) {
    const float* x   = (const float*)d_in[0];
    const float* Pi  = (const float*)d_in[1];
    const float* cbk = (const float*)d_in[2];
    float* out = (float*)d_out;

    int ntok = in_sizes[0] / 128;
    int blocks = ntok / 64;

    cudaFuncSetAttribute(tq_fused, cudaFuncAttributeMaxDynamicSharedMemorySize, SMEM_BYTES);
    tq_fused<<<blocks, 256, SMEM_BYTES>>>(x, Pi, cbk, out);
}

// round 12
// speedup vs baseline: 1.5006x; 1.2566x over previous
#include <cuda_runtime.h>
#include <cuda_fp16.h>
#include <cstdint>

typedef uint32_t u32;

#define SQRTD_F 11.313708498984761f
#define RSB 272            // row stride bytes (136 halves = 17 x 16B chunks)

// smem byte offsets
#define SM_PIH  0          // Pi hi : 128*272 = 34816
#define SM_PIL  34816      // Pi lo
#define SM_AH   69632      // A hi : 64*272 = 17408
#define SM_AL   87040      // A lo
#define SM_MISC 104448
#define SMEM_BYTES 106496

static __device__ __forceinline__ u32 smem_u32(const void* p) {
    u32 r;
    asm("{ .reg .u64 t; cvta.to.shared.u64 t, %1; cvt.u32.u64 %0, t; }" : "=r"(r) : "l"(p));
    return r;
}
static __device__ __forceinline__ u32 hpack(__half a, __half b) {
    return (u32)__half_as_ushort(a) | ((u32)__half_as_ushort(b) << 16);
}
static __device__ __forceinline__ int csw(int c) { return c ^ ((c & 8) >> 1); }

static __device__ __forceinline__ void mma16(float c[4], u32 a0, u32 a1, u32 a2, u32 a3,
                                             u32 b0, u32 b1) {
    asm volatile(
        "mma.sync.aligned.m16n8k16.row.col.f32.f16.f16.f32 "
        "{%0,%1,%2,%3},{%4,%5,%6,%7},{%8,%9},{%0,%1,%2,%3};"
        : "+f"(c[0]), "+f"(c[1]), "+f"(c[2]), "+f"(c[3])
        : "r"(a0), "r"(a1), "r"(a2), "r"(a3), "r"(b0), "r"(b1));
}
#define LDSM_X4(r, a) \
    asm volatile("ldmatrix.sync.aligned.m8n8.x4.shared.b16 {%0,%1,%2,%3}, [%4];" \
        : "=r"((r)[0]), "=r"((r)[1]), "=r"((r)[2]), "=r"((r)[3]) : "r"(a))
#define LDSM_X4T(r, a) \
    asm volatile("ldmatrix.sync.aligned.m8n8.x4.trans.shared.b16 {%0,%1,%2,%3}, [%4];" \
        : "=r"((r)[0]), "=r"((r)[1]), "=r"((r)[2]), "=r"((r)[3]) : "r"(a))

// pack 8 floats (one 16B fp16 chunk) into hi/lo uint4 and store at swizzled chunk
static __device__ __forceinline__ void stage_chunk(char* base, int row, int c,
                                                   const float4 a, const float4 b,
                                                   int lo_off) {
    __half h0 = __float2half_rn(a.x), h1 = __float2half_rn(a.y);
    __half h2 = __float2half_rn(a.z), h3 = __float2half_rn(a.w);
    __half h4 = __float2half_rn(b.x), h5 = __float2half_rn(b.y);
    __half h6 = __float2half_rn(b.z), h7 = __float2half_rn(b.w);
    uint4 hi, lo;
    hi.x = hpack(h0, h1); hi.y = hpack(h2, h3);
    hi.z = hpack(h4, h5); hi.w = hpack(h6, h7);
    lo.x = hpack(__float2half_rn(a.x - __half2float(h0)),
                 __float2half_rn(a.y - __half2float(h1)));
    lo.y = hpack(__float2half_rn(a.z - __half2float(h2)),
                 __float2half_rn(a.w - __half2float(h3)));
    lo.z = hpack(__float2half_rn(b.x - __half2float(h4)),
                 __float2half_rn(b.y - __half2float(h5)));
    lo.w = hpack(__float2half_rn(b.z - __half2float(h6)),
                 __float2half_rn(b.w - __half2float(h7)));
    char* p = base + row * RSB + csw(c) * 16;
    *(uint4*)p = hi;
    *(uint4*)(p + lo_off) = lo;
}

__global__ __launch_bounds__(256, 2)
void tq_fused(const float* __restrict__ x, const float* __restrict__ Pi,
              const float* __restrict__ cbk, float* __restrict__ out) {
    extern __shared__ char sm[];
    __half* s_csdh  = (__half*)(sm + SM_MISC);          // 16 fp16
    float*  s_mid   = (float*)(sm + SM_MISC + 64);      // 15 f32
    float*  s_part  = (float*)(sm + SM_MISC + 192);     // 256 f32
    float*  s_scale = (float*)(sm + SM_MISC + 1216);    // 64 f32
    float*  s_nh    = (float*)(sm + SM_MISC + 1472);    // 64 f32

    const int tid = threadIdx.x;
    const int wid = tid >> 5, lane = tid & 31;
    const int g = lane >> 2, t = lane & 3;
    const int mrow0 = (wid >> 2) * 32;    // 2 M groups (64 token rows)
    const int ncol0 = (wid & 3) * 32;     // 4 N groups (128 cols)
    const int tok0 = blockIdx.x << 6;     // 64 tokens / CTA

    // ---- stage Pi hi/lo (2 threads/row, conflict-free STS.128) ----
    {
        const int r = tid >> 1, h = tid & 1;
        const float4* pp = (const float4*)(Pi + r * 128 + h * 64);
        #pragma unroll
        for (int e2 = 0; e2 < 8; e2++)
            stage_chunk(sm + SM_PIH, r, 8 * h + e2, pp[2 * e2], pp[2 * e2 + 1],
                        SM_PIL - SM_PIH);
    }
    // ---- load x (4 threads/token); stage A hi/lo (raw x); partial SS ----
    {
        const int r = tid >> 2, q = tid & 3;
        const float4* xr = (const float4*)(x + (size_t)(tok0 + r) * 128 + q * 32);
        float ss = 0.f;
        #pragma unroll
        for (int e2 = 0; e2 < 4; e2++) {
            float4 a = xr[2 * e2], b = xr[2 * e2 + 1];
            ss += a.x * a.x + a.y * a.y + a.z * a.z + a.w * a.w;
            ss += b.x * b.x + b.y * b.y + b.z * b.z + b.w * b.w;
            stage_chunk(sm + SM_AH, r, 4 * q + e2, a, b, SM_AL - SM_AH);
        }
        s_part[tid] = ss;
    }
    if (tid < 16) {
        float c = cbk[tid];
        s_csdh[tid] = __float2half_rn(__fdiv_rn(c, SQRTD_F));
        if (tid < 15) s_mid[tid] = (c + cbk[tid + 1]) * 0.5f;
    }
    __syncthreads();

    // ---- norms (warps 0-1; other warps proceed into fwd chain) ----
    if (tid < 64) {
        float s = s_part[4 * tid] + s_part[4 * tid + 1]
                + s_part[4 * tid + 2] + s_part[4 * tid + 3];
        float n = __fsqrt_rn(s);
        float cn = fmaxf(n, 1e-8f);
        s_scale[tid] = __fdiv_rn(SQRTD_F, cn);
        s_nh[tid] = __half2float(__float2half_rn(n));
    }

    // per-thread LDSM lane geometry
    const u32 sb = smem_u32(sm);
    const int lrow = (lane & 7) + ((lane >> 3) & 1) * 8;   // 0..15
    const int lq = lane >> 4;                               // chunk select
    const u32 aAh0 = sb + SM_AH + (u32)(mrow0 + lrow) * RSB;
    const u32 aAh1 = aAh0 + 16 * RSB;
    const u32 aAl0 = aAh0 + (SM_AL - SM_AH);
    const u32 aAl1 = aAh1 + (SM_AL - SM_AH);
    const u32 aBh0 = sb + SM_PIH + (u32)(ncol0 + lrow) * RSB;
    const u32 aBh1 = aBh0 + 16 * RSB;
    const u32 aBl0 = aBh0 + (SM_PIL - SM_PIH);
    const u32 aBl1 = aBh1 + (SM_PIL - SM_PIH);

    float acc[2][4][4];
    #pragma unroll
    for (int i = 0; i < 2; i++)
        #pragma unroll
        for (int j = 0; j < 4; j++)
            #pragma unroll
            for (int k = 0; k < 4; k++) acc[i][j][k] = 0.f;

    // ---- forward: y_raw = x @ Pi^T (3-product hi/lo fp16) ----
    #pragma unroll 1
    for (int ks = 0; ks < 8; ks++) {
        const u32 co = (u32)(((2 * ks) ^ (ks & 4)) + lq) * 16;
        u32 bh0[4], bh1[4], bl0[4], bl1[4], ah0[4], ah1[4], al0[4], al1[4];
        LDSM_X4(bh0, aBh0 + co);
        LDSM_X4(bh1, aBh1 + co);
        LDSM_X4(bl0, aBl0 + co);
        LDSM_X4(bl1, aBl1 + co);
        LDSM_X4(ah0, aAh0 + co);
        LDSM_X4(ah1, aAh1 + co);
        LDSM_X4(al0, aAl0 + co);
        LDSM_X4(al1, aAl1 + co);
        u32 bh[4][2] = {{bh0[0],bh0[2]},{bh0[1],bh0[3]},{bh1[0],bh1[2]},{bh1[1],bh1[3]}};
        u32 bl[4][2] = {{bl0[0],bl0[2]},{bl0[1],bl0[3]},{bl1[0],bl1[2]},{bl1[1],bl1[3]}};
        #pragma unroll
        for (int nt = 0; nt < 4; nt++) {
            mma16(acc[0][nt], ah0[0], ah0[1], ah0[2], ah0[3], bh[nt][0], bh[nt][1]);
            mma16(acc[1][nt], ah1[0], ah1[1], ah1[2], ah1[3], bh[nt][0], bh[nt][1]);
        }
        #pragma unroll
        for (int nt = 0; nt < 4; nt++) {
            mma16(acc[0][nt], ah0[0], ah0[1], ah0[2], ah0[3], bl[nt][0], bl[nt][1]);
            mma16(acc[1][nt], ah1[0], ah1[1], ah1[2], ah1[3], bl[nt][0], bl[nt][1]);
        }
        #pragma unroll
        for (int nt = 0; nt < 4; nt++) {
            mma16(acc[0][nt], al0[0], al0[1], al0[2], al0[3], bh[nt][0], bh[nt][1]);
            mma16(acc[1][nt], al1[0], al1[1], al1[2], al1[3], bh[nt][0], bh[nt][1]);
        }
    }
    __syncthreads();

    // ---- quantize: y = y_raw*(sqrt_d/norm); write u32 csd-pairs into A hi ----
    {
        float mids[15];
        #pragma unroll
        for (int l = 0; l < 15; l++) mids[l] = s_mid[l];
        u32* aW = (u32*)(sm + SM_AH);
        #pragma unroll
        for (int mt = 0; mt < 2; mt++) {
            const int row0 = mrow0 + mt * 16 + g;
            const float sc0 = s_scale[row0];
            const float sc1 = s_scale[row0 + 8];
            #pragma unroll
            for (int nt = 0; nt < 4; nt++) {
                const int p = (ncol0 >> 1) + nt * 4 + t;      // k-pair index
                const int woff = csw(p >> 2) * 4 + (p & 3);   // u32 within row
                {
                    float y0 = acc[mt][nt][0] * sc0, y1 = acc[mt][nt][1] * sc0;
                    int i0 = 0, i1 = 0;
                    #pragma unroll
                    for (int l = 0; l < 15; l++) { i0 += (y0 > mids[l]); i1 += (y1 > mids[l]); }
                    aW[row0 * 68 + woff] = hpack(s_csdh[i0], s_csdh[i1]);
                }
                {
                    float y0 = acc[mt][nt][2] * sc1, y1 = acc[mt][nt][3] * sc1;
                    int i0 = 0, i1 = 0;
                    #pragma unroll
                    for (int l = 0; l < 15; l++) { i0 += (y0 > mids[l]); i1 += (y1 > mids[l]); }
                    aW[(row0 + 8) * 68 + woff] = hpack(s_csdh[i0], s_csdh[i1]);
                }
                acc[mt][nt][0] = 0.f; acc[mt][nt][1] = 0.f;
                acc[mt][nt][2] = 0.f; acc[mt][nt][3] = 0.f;
            }
        }
    }
    __syncthreads();

    // ---- backward: z = a_hat @ Pi (2-product), B via ldmatrix.trans of Pi tiles ----
    {
        // per-thread chunk constants for trans loads (i-chunks)
        const int cnq = (ncol0 >> 3) + lq;
        const u32 cb0 = (u32)csw(cnq) * 16;
        const u32 cb1 = (u32)csw(cnq + 2) * 16;
        const u32 tbase = sb + SM_PIH + (u32)lrow * RSB;
        #pragma unroll 1
        for (int ks = 0; ks < 8; ks++) {
            const u32 rb = tbase + (u32)(16 * ks) * RSB;
            const u32 rbl = rb + (SM_PIL - SM_PIH);
            const u32 co = (u32)(((2 * ks) ^ (ks & 4)) + lq) * 16;
            u32 th0[4], th1[4], tl0[4], tl1[4], ah0[4], ah1[4];
            LDSM_X4T(th0, rb + cb0);
            LDSM_X4T(th1, rb + cb1);
            LDSM_X4T(tl0, rbl + cb0);
            LDSM_X4T(tl1, rbl + cb1);
            LDSM_X4(ah0, aAh0 + co);
            LDSM_X4(ah1, aAh1 + co);
            u32 bh[4][2] = {{th0[0],th0[1]},{th0[2],th0[3]},{th1[0],th1[1]},{th1[2],th1[3]}};
            u32 bl[4][2] = {{tl0[0],tl0[1]},{tl0[2],tl0[3]},{tl1[0],tl1[1]},{tl1[2],tl1[3]}};
            #pragma unroll
            for (int nt = 0; nt < 4; nt++) {
                mma16(acc[0][nt], ah0[0], ah0[1], ah0[2], ah0[3], bh[nt][0], bh[nt][1]);
                mma16(acc[1][nt], ah1[0], ah1[1], ah1[2], ah1[3], bh[nt][0], bh[nt][1]);
            }
            #pragma unroll
            for (int nt = 0; nt < 4; nt++) {
                mma16(acc[0][nt], ah0[0], ah0[1], ah0[2], ah0[3], bl[nt][0], bl[nt][1]);
                mma16(acc[1][nt], ah1[0], ah1[1], ah1[2], ah1[3], bl[nt][0], bl[nt][1]);
            }
        }
    }

    // ---- epilogue: scale by fp16-roundtripped norm, store float2 ----
    #pragma unroll
    for (int mt = 0; mt < 2; mt++) {
        #pragma unroll
        for (int nt = 0; nt < 4; nt++) {
            int row0 = mrow0 + mt * 16 + g;
            int col  = ncol0 + nt * 8 + 2 * t;
            float nh0 = s_nh[row0];
            float nh1 = s_nh[row0 + 8];
            *(float2*)(out + (size_t)(tok0 + row0) * 128 + col) =
                make_float2(acc[mt][nt][0] * nh0, acc[mt][nt][1] * nh0);
            *(float2*)(out + (size_t)(tok0 + row0 + 8) * 128 + col) =
                make_float2(acc[mt][nt][2] * nh1, acc[mt][nt][3] * nh1);
        }
    }
}

extern "C" void kernel_launch(void* const* d_in, const int* in_sizes, int n_in,
                              void* d_out, int out_size) {
    const float* x   = (const float*)d_in[0];
    const float* Pi  = (const float*)d_in[1];
    const float* cbk = (const float*)d_in[2];
    float* out = (float*)d_out;

    int ntok = in_sizes[0] / 128;
    int blocks = ntok / 64;

    cudaFuncSetAttribute(tq_fused, cudaFuncAttributeMaxDynamicSharedMemorySize, SMEM_BYTES);
    tq_fused<<<blocks, 256, SMEM_BYTES>>>(x, Pi, cbk, out);
}

// round 13
// speedup vs baseline: 1.7503x; 1.1664x over previous
#include <cuda_runtime.h>
#include <cuda_fp16.h>
#include <cstdint>

typedef uint32_t u32;

#define SQRTD_F 11.313708498984761f
#define RSB 272            // row stride bytes (17 x 16B chunks)

// smem byte offsets
#define SM_PIH  0          // Pi hi : 128*272 = 34816
#define SM_PIL  34816      // Pi lo
#define SM_AH   69632      // A hi : 64*272 = 17408
#define SM_AL   87040      // A lo
#define SM_MISC 104448
#define SMEM_BYTES 106496

// precomputed packed Pi (hi tile then lo tile, smem-identical layout) + tables
__device__ uint4  g_pip[4352];
__device__ __half g_csdh[16];
__device__ float  g_mid[15];

static __device__ __forceinline__ u32 smem_u32(const void* p) {
    u32 r;
    asm("{ .reg .u64 t; cvta.to.shared.u64 t, %1; cvt.u32.u64 %0, t; }" : "=r"(r) : "l"(p));
    return r;
}
static __device__ __forceinline__ u32 hpack(__half a, __half b) {
    return (u32)__half_as_ushort(a) | ((u32)__half_as_ushort(b) << 16);
}
static __device__ __forceinline__ int csw(int c) { return c ^ ((c & 8) >> 1); }

static __device__ __forceinline__ void mma16(float c[4], u32 a0, u32 a1, u32 a2, u32 a3,
                                             u32 b0, u32 b1) {
    asm volatile(
        "mma.sync.aligned.m16n8k16.row.col.f32.f16.f16.f32 "
        "{%0,%1,%2,%3},{%4,%5,%6,%7},{%8,%9},{%0,%1,%2,%3};"
        : "+f"(c[0]), "+f"(c[1]), "+f"(c[2]), "+f"(c[3])
        : "r"(a0), "r"(a1), "r"(a2), "r"(a3), "r"(b0), "r"(b1));
}
#define LDSM_X4(r, a) \
    asm volatile("ldmatrix.sync.aligned.m8n8.x4.shared.b16 {%0,%1,%2,%3}, [%4];" \
        : "=r"((r)[0]), "=r"((r)[1]), "=r"((r)[2]), "=r"((r)[3]) : "r"(a))
#define LDSM_X4T(r, a) \
    asm volatile("ldmatrix.sync.aligned.m8n8.x4.trans.shared.b16 {%0,%1,%2,%3}, [%4];" \
        : "=r"((r)[0]), "=r"((r)[1]), "=r"((r)[2]), "=r"((r)[3]) : "r"(a))
#define CP16(s, g) \
    asm volatile("cp.async.cg.shared.global [%0], [%1], 16;" :: "r"(s), "l"(g))

// pack 8 floats into hi/lo uint4
static __device__ __forceinline__ void pack8(const float4 a, const float4 b,
                                             uint4& hi, uint4& lo) {
    __half h0 = __float2half_rn(a.x), h1 = __float2half_rn(a.y);
    __half h2 = __float2half_rn(a.z), h3 = __float2half_rn(a.w);
    __half h4 = __float2half_rn(b.x), h5 = __float2half_rn(b.y);
    __half h6 = __float2half_rn(b.z), h7 = __float2half_rn(b.w);
    hi.x = hpack(h0, h1); hi.y = hpack(h2, h3);
    hi.z = hpack(h4, h5); hi.w = hpack(h6, h7);
    lo.x = hpack(__float2half_rn(a.x - __half2float(h0)),
                 __float2half_rn(a.y - __half2float(h1)));
    lo.y = hpack(__float2half_rn(a.z - __half2float(h2)),
                 __float2half_rn(a.w - __half2float(h3)));
    lo.z = hpack(__float2half_rn(b.x - __half2float(h4)),
                 __float2half_rn(b.y - __half2float(h5)));
    lo.w = hpack(__float2half_rn(b.z - __half2float(h6)),
                 __float2half_rn(b.w - __half2float(h7)));
}

// ---------------- setup kernel: pack Pi + tables once per launch ----------------
__global__ __launch_bounds__(256)
void tq_setup(const float* __restrict__ Pi, const float* __restrict__ cbk) {
    const int tid = threadIdx.x;
    const int r = blockIdx.x * 16 + (tid >> 4);
    const int c = tid & 15;
    const float4* pp = (const float4*)(Pi + r * 128 + c * 8);
    uint4 hi, lo;
    pack8(pp[0], pp[1], hi, lo);
    g_pip[r * 17 + csw(c)] = hi;
    g_pip[2176 + r * 17 + csw(c)] = lo;
    if (c == 0) {   // zero the pad chunk
        uint4 z = make_uint4(0, 0, 0, 0);
        g_pip[r * 17 + 16] = z;
        g_pip[2176 + r * 17 + 16] = z;
    }
    if (blockIdx.x == 0 && tid < 16) {
        float cv = cbk[tid];
        g_csdh[tid] = __float2half_rn(__fdiv_rn(cv, SQRTD_F));
        if (tid < 15) g_mid[tid] = (cv + cbk[tid + 1]) * 0.5f;
    }
}

// ---------------- main kernel ----------------
__global__ __launch_bounds__(256, 2)
void tq_fused(const float* __restrict__ x, float* __restrict__ out) {
    extern __shared__ char sm[];
    __half* s_csdh  = (__half*)(sm + SM_MISC);          // 16 fp16
    float*  s_mid   = (float*)(sm + SM_MISC + 64);      // 15 f32
    float*  s_part  = (float*)(sm + SM_MISC + 192);     // 256 f32
    float*  s_scale = (float*)(sm + SM_MISC + 1216);    // 64 f32
    float*  s_nh    = (float*)(sm + SM_MISC + 1472);    // 64 f32

    const int tid = threadIdx.x;
    const int wid = tid >> 5, lane = tid & 31;
    const int g = lane >> 2, t = lane & 3;
    const int mrow0 = (wid >> 2) * 32;
    const int ncol0 = (wid & 3) * 32;
    const int tok0 = blockIdx.x << 6;

    const u32 sb = smem_u32(sm);

    // ---- copy packed Pi tiles (hi+lo) via cp.async, 17 x 16B per thread ----
    {
        const uint4* gp = g_pip;
        #pragma unroll
        for (int i = 0; i < 17; i++) {
            const int idx = tid + i * 256;
            CP16(sb + SM_PIH + idx * 16, gp + idx);
        }
        asm volatile("cp.async.commit_group;" ::: "memory");
    }

    // ---- load x (4 threads/token); stage A hi/lo (raw x); partial SS ----
    {
        const int r = tid >> 2, q = tid & 3;
        const float4* xr = (const float4*)(x + (size_t)(tok0 + r) * 128 + q * 32);
        float ss = 0.f;
        #pragma unroll
        for (int e2 = 0; e2 < 4; e2++) {
            float4 a = xr[2 * e2], b = xr[2 * e2 + 1];
            ss += a.x * a.x + a.y * a.y + a.z * a.z + a.w * a.w;
            ss += b.x * b.x + b.y * b.y + b.z * b.z + b.w * b.w;
            uint4 hi, lo;
            pack8(a, b, hi, lo);
            char* p = sm + SM_AH + r * RSB + csw(4 * q + e2) * 16;
            *(uint4*)p = hi;
            *(uint4*)(p + (SM_AL - SM_AH)) = lo;
        }
        s_part[tid] = ss;
    }
    if (tid < 16) {
        s_csdh[tid] = g_csdh[tid];
        if (tid < 15) s_mid[tid] = g_mid[tid];
    }
    asm volatile("cp.async.wait_group 0;" ::: "memory");
    __syncthreads();

    // ---- norms (warps 0-1; other warps proceed into fwd chain) ----
    if (tid < 64) {
        float s = s_part[4 * tid] + s_part[4 * tid + 1]
                + s_part[4 * tid + 2] + s_part[4 * tid + 3];
        float n = __fsqrt_rn(s);
        float cn = fmaxf(n, 1e-8f);
        s_scale[tid] = __fdiv_rn(SQRTD_F, cn);
        s_nh[tid] = __half2float(__float2half_rn(n));
    }

    // per-thread LDSM lane geometry
    const int lrow = (lane & 7) + ((lane >> 3) & 1) * 8;
    const int lq = lane >> 4;
    const u32 aAh0 = sb + SM_AH + (u32)(mrow0 + lrow) * RSB;
    const u32 aAh1 = aAh0 + 16 * RSB;
    const u32 aAl0 = aAh0 + (SM_AL - SM_AH);
    const u32 aAl1 = aAh1 + (SM_AL - SM_AH);
    const u32 aBh0 = sb + SM_PIH + (u32)(ncol0 + lrow) * RSB;
    const u32 aBh1 = aBh0 + 16 * RSB;
    const u32 aBl0 = aBh0 + (SM_PIL - SM_PIH);
    const u32 aBl1 = aBh1 + (SM_PIL - SM_PIH);

    float acc[2][4][4];
    #pragma unroll
    for (int i = 0; i < 2; i++)
        #pragma unroll
        for (int j = 0; j < 4; j++)
            #pragma unroll
            for (int k = 0; k < 4; k++) acc[i][j][k] = 0.f;

    // ---- forward: y_raw = x @ Pi^T (3-product hi/lo fp16) ----
    #pragma unroll 1
    for (int ks = 0; ks < 8; ks++) {
        const u32 co = (u32)(((2 * ks) ^ (ks & 4)) + lq) * 16;
        u32 bh0[4], bh1[4], bl0[4], bl1[4], ah0[4], ah1[4], al0[4], al1[4];
        LDSM_X4(bh0, aBh0 + co);
        LDSM_X4(bh1, aBh1 + co);
        LDSM_X4(bl0, aBl0 + co);
        LDSM_X4(bl1, aBl1 + co);
        LDSM_X4(ah0, aAh0 + co);
        LDSM_X4(ah1, aAh1 + co);
        LDSM_X4(al0, aAl0 + co);
        LDSM_X4(al1, aAl1 + co);
        u32 bh[4][2] = {{bh0[0],bh0[2]},{bh0[1],bh0[3]},{bh1[0],bh1[2]},{bh1[1],bh1[3]}};
        u32 bl[4][2] = {{bl0[0],bl0[2]},{bl0[1],bl0[3]},{bl1[0],bl1[2]},{bl1[1],bl1[3]}};
        #pragma unroll
        for (int nt = 0; nt < 4; nt++) {
            mma16(acc[0][nt], ah0[0], ah0[1], ah0[2], ah0[3], bh[nt][0], bh[nt][1]);
            mma16(acc[1][nt], ah1[0], ah1[1], ah1[2], ah1[3], bh[nt][0], bh[nt][1]);
        }
        #pragma unroll
        for (int nt = 0; nt < 4; nt++) {
            mma16(acc[0][nt], ah0[0], ah0[1], ah0[2], ah0[3], bl[nt][0], bl[nt][1]);
            mma16(acc[1][nt], ah1[0], ah1[1], ah1[2], ah1[3], bl[nt][0], bl[nt][1]);
        }
        #pragma unroll
        for (int nt = 0; nt < 4; nt++) {
            mma16(acc[0][nt], al0[0], al0[1], al0[2], al0[3], bh[nt][0], bh[nt][1]);
            mma16(acc[1][nt], al1[0], al1[1], al1[2], al1[3], bh[nt][0], bh[nt][1]);
        }
    }
    __syncthreads();

    // ---- quantize: y = y_raw*(sqrt_d/norm); write u32 csd-pairs into A hi ----
    {
        float mids[15];
        #pragma unroll
        for (int l = 0; l < 15; l++) mids[l] = s_mid[l];
        u32* aW = (u32*)(sm + SM_AH);
        #pragma unroll
        for (int mt = 0; mt < 2; mt++) {
            const int row0 = mrow0 + mt * 16 + g;
            const float sc0 = s_scale[row0];
            const float sc1 = s_scale[row0 + 8];
            #pragma unroll
            for (int nt = 0; nt < 4; nt++) {
                const int p = (ncol0 >> 1) + nt * 4 + t;
                const int woff = csw(p >> 2) * 4 + (p & 3);
                {
                    float y0 = acc[mt][nt][0] * sc0, y1 = acc[mt][nt][1] * sc0;
                    int i0 = 0, i1 = 0;
                    #pragma unroll
                    for (int l = 0; l < 15; l++) { i0 += (y0 > mids[l]); i1 += (y1 > mids[l]); }
                    aW[row0 * 68 + woff] = hpack(s_csdh[i0], s_csdh[i1]);
                }
                {
                    float y0 = acc[mt][nt][2] * sc1, y1 = acc[mt][nt][3] * sc1;
                    int i0 = 0, i1 = 0;
                    #pragma unroll
                    for (int l = 0; l < 15; l++) { i0 += (y0 > mids[l]); i1 += (y1 > mids[l]); }
                    aW[(row0 + 8) * 68 + woff] = hpack(s_csdh[i0], s_csdh[i1]);
                }
                acc[mt][nt][0] = 0.f; acc[mt][nt][1] = 0.f;
                acc[mt][nt][2] = 0.f; acc[mt][nt][3] = 0.f;
            }
        }
    }
    __syncthreads();

    // ---- backward: z = a_hat @ Pi (2-product), B via ldmatrix.trans of Pi tiles ----
    {
        const int cnq = (ncol0 >> 3) + lq;
        const u32 cb0 = (u32)csw(cnq) * 16;
        const u32 cb1 = (u32)csw(cnq + 2) * 16;
        const u32 tbase = sb + SM_PIH + (u32)lrow * RSB;
        #pragma unroll 1
        for (int ks = 0; ks < 8; ks++) {
            const u32 rb = tbase + (u32)(16 * ks) * RSB;
            const u32 rbl = rb + (SM_PIL - SM_PIH);
            const u32 co = (u32)(((2 * ks) ^ (ks & 4)) + lq) * 16;
            u32 th0[4], th1[4], tl0[4], tl1[4], ah0[4], ah1[4];
            LDSM_X4T(th0, rb + cb0);
            LDSM_X4T(th1, rb + cb1);
            LDSM_X4T(tl0, rbl + cb0);
            LDSM_X4T(tl1, rbl + cb1);
            LDSM_X4(ah0, aAh0 + co);
            LDSM_X4(ah1, aAh1 + co);
            u32 bh[4][2] = {{th0[0],th0[1]},{th0[2],th0[3]},{th1[0],th1[1]},{th1[2],th1[3]}};
            u32 bl[4][2] = {{tl0[0],tl0[1]},{tl0[2],tl0[3]},{tl1[0],tl1[1]},{tl1[2],tl1[3]}};
            #pragma unroll
            for (int nt = 0; nt < 4; nt++) {
                mma16(acc[0][nt], ah0[0], ah0[1], ah0[2], ah0[3], bh[nt][0], bh[nt][1]);
                mma16(acc[1][nt], ah1[0], ah1[1], ah1[2], ah1[3], bh[nt][0], bh[nt][1]);
            }
            #pragma unroll
            for (int nt = 0; nt < 4; nt++) {
                mma16(acc[0][nt], ah0[0], ah0[1], ah0[2], ah0[3], bl[nt][0], bl[nt][1]);
                mma16(acc[1][nt], ah1[0], ah1[1], ah1[2], ah1[3], bl[nt][0], bl[nt][1]);
            }
        }
    }

    // ---- epilogue: scale by fp16-roundtripped norm, store float2 ----
    #pragma unroll
    for (int mt = 0; mt < 2; mt++) {
        #pragma unroll
        for (int nt = 0; nt < 4; nt++) {
            int row0 = mrow0 + mt * 16 + g;
            int col  = ncol0 + nt * 8 + 2 * t;
            float nh0 = s_nh[row0];
            float nh1 = s_nh[row0 + 8];
            *(float2*)(out + (size_t)(tok0 + row0) * 128 + col) =
                make_float2(acc[mt][nt][0] * nh0, acc[mt][nt][1] * nh0);
            *(float2*)(out + (size_t)(tok0 + row0 + 8) * 128 + col) =
                make_float2(acc[mt][nt][2] * nh1, acc[mt][nt][3] * nh1);
        }
    }
}

extern "C" void kernel_launch(void* const* d_in, const int* in_sizes, int n_in,
                              void* d_out, int out_size) {
    const float* x   = (const float*)d_in[0];
    const float* Pi  = (const float*)d_in[1];
    const float* cbk = (const float*)d_in[2];
    float* out = (float*)d_out;

    int ntok = in_sizes[0] / 128;
    int blocks = ntok / 64;

    cudaFuncSetAttribute(tq_fused, cudaFuncAttributeMaxDynamicSharedMemorySize, SMEM_BYTES);
    tq_setup<<<8, 256>>>(Pi, cbk);
    tq_fused<<<blocks, 256, SMEM_BYTES>>>(x, out);
}

// round 14
// speedup vs baseline: 1.9624x; 1.1212x over previous
#include <cuda_runtime.h>
#include <cuda_fp16.h>
#include <cstdint>

typedef uint32_t u32;

#define SQRTD_F 11.313708498984761f
#define RSB 272            // row stride bytes (17 x 16B chunks)

// smem byte offsets
#define SM_PIH  0          // Pi hi : 128*272 = 34816
#define SM_PIL  34816      // Pi lo
#define SM_AH   69632      // A hi : 64*272 = 17408
#define SM_AL   87040      // A lo
#define SM_MISC 104448
#define SMEM_BYTES 106496

// precomputed packed Pi (hi tile then lo tile, smem-identical layout) + tables
__device__ uint4  g_pip[4352];
__device__ __half g_csdh[16];
__device__ float  g_mid[15];

static __device__ __forceinline__ u32 smem_u32(const void* p) {
    u32 r;
    asm("{ .reg .u64 t; cvta.to.shared.u64 t, %1; cvt.u32.u64 %0, t; }" : "=r"(r) : "l"(p));
    return r;
}
static __device__ __forceinline__ u32 hpack(__half a, __half b) {
    return (u32)__half_as_ushort(a) | ((u32)__half_as_ushort(b) << 16);
}
static __device__ __forceinline__ int csw(int c) { return c ^ ((c & 8) >> 1); }

static __device__ __forceinline__ void mma16(float c[4], u32 a0, u32 a1, u32 a2, u32 a3,
                                             u32 b0, u32 b1) {
    asm volatile(
        "mma.sync.aligned.m16n8k16.row.col.f32.f16.f16.f32 "
        "{%0,%1,%2,%3},{%4,%5,%6,%7},{%8,%9},{%0,%1,%2,%3};"
        : "+f"(c[0]), "+f"(c[1]), "+f"(c[2]), "+f"(c[3])
        : "r"(a0), "r"(a1), "r"(a2), "r"(a3), "r"(b0), "r"(b1));
}
#define LDSM_X4(r, a) \
    asm volatile("ldmatrix.sync.aligned.m8n8.x4.shared.b16 {%0,%1,%2,%3}, [%4];" \
        : "=r"((r)[0]), "=r"((r)[1]), "=r"((r)[2]), "=r"((r)[3]) : "r"(a))
#define LDSM_X4T(r, a) \
    asm volatile("ldmatrix.sync.aligned.m8n8.x4.trans.shared.b16 {%0,%1,%2,%3}, [%4];" \
        : "=r"((r)[0]), "=r"((r)[1]), "=r"((r)[2]), "=r"((r)[3]) : "r"(a))
#define CP16(s, g) \
    asm volatile("cp.async.cg.shared.global [%0], [%1], 16;" :: "r"(s), "l"(g))

// exact binary-search quantizer: idx = #{l : y > mid[l]} for sorted mids
static __device__ __forceinline__ int quant_idx(float y, const float* m) {
    bool b3 = y > m[7];
    float mA = b3 ? m[11] : m[3];
    bool b2 = y > mA;
    float mB = b3 ? (b2 ? m[13] : m[9]) : (b2 ? m[5] : m[1]);
    bool b1 = y > mB;
    float mC = b3 ? (b2 ? (b1 ? m[14] : m[12]) : (b1 ? m[10] : m[8]))
                  : (b2 ? (b1 ? m[6]  : m[4])  : (b1 ? m[2]  : m[0]));
    bool b0 = y > mC;
    return (((int)b3) << 3) | (((int)b2) << 2) | (((int)b1) << 1) | (int)b0;
}

// pack 8 floats into hi/lo uint4
static __device__ __forceinline__ void pack8(const float4 a, const float4 b,
                                             uint4& hi, uint4& lo) {
    __half h0 = __float2half_rn(a.x), h1 = __float2half_rn(a.y);
    __half h2 = __float2half_rn(a.z), h3 = __float2half_rn(a.w);
    __half h4 = __float2half_rn(b.x), h5 = __float2half_rn(b.y);
    __half h6 = __float2half_rn(b.z), h7 = __float2half_rn(b.w);
    hi.x = hpack(h0, h1); hi.y = hpack(h2, h3);
    hi.z = hpack(h4, h5); hi.w = hpack(h6, h7);
    lo.x = hpack(__float2half_rn(a.x - __half2float(h0)),
                 __float2half_rn(a.y - __half2float(h1)));
    lo.y = hpack(__float2half_rn(a.z - __half2float(h2)),
                 __float2half_rn(a.w - __half2float(h3)));
    lo.z = hpack(__float2half_rn(b.x - __half2float(h4)),
                 __float2half_rn(b.y - __half2float(h5)));
    lo.w = hpack(__float2half_rn(b.z - __half2float(h6)),
                 __float2half_rn(b.w - __half2float(h7)));
}

// ---------------- setup kernel: pack Pi + tables once per launch ----------------
__global__ __launch_bounds__(256)
void tq_setup(const float* __restrict__ Pi, const float* __restrict__ cbk) {
    const int tid = threadIdx.x;
    const int r = blockIdx.x * 16 + (tid >> 4);
    const int c = tid & 15;
    const float4* pp = (const float4*)(Pi + r * 128 + c * 8);
    uint4 hi, lo;
    pack8(pp[0], pp[1], hi, lo);
    g_pip[r * 17 + csw(c)] = hi;
    g_pip[2176 + r * 17 + csw(c)] = lo;
    if (c == 0) {
        uint4 z = make_uint4(0, 0, 0, 0);
        g_pip[r * 17 + 16] = z;
        g_pip[2176 + r * 17 + 16] = z;
    }
    if (blockIdx.x == 0 && tid < 16) {
        float cv = cbk[tid];
        g_csdh[tid] = __float2half_rn(__fdiv_rn(cv, SQRTD_F));
        if (tid < 15) g_mid[tid] = (cv + cbk[tid + 1]) * 0.5f;
    }
}

// ---------------- main kernel ----------------
__global__ __launch_bounds__(256, 2)
void tq_fused(const float* __restrict__ x, float* __restrict__ out) {
    extern __shared__ char sm[];
    __half* s_csdh  = (__half*)(sm + SM_MISC);          // 16 fp16
    float*  s_mid   = (float*)(sm + SM_MISC + 64);      // 15 f32
    float*  s_part  = (float*)(sm + SM_MISC + 192);     // 256 f32
    float*  s_scale = (float*)(sm + SM_MISC + 1216);    // 64 f32
    float*  s_nh    = (float*)(sm + SM_MISC + 1472);    // 64 f32

    const int tid = threadIdx.x;
    const int wid = tid >> 5, lane = tid & 31;
    const int g = lane >> 2, t = lane & 3;
    const int mrow0 = (wid >> 2) * 32;
    const int ncol0 = (wid & 3) * 32;
    const int tok0 = blockIdx.x << 6;

    const u32 sb = smem_u32(sm);

    // ---- copy packed Pi tiles (hi+lo) via cp.async, 17 x 16B per thread ----
    {
        const uint4* gp = g_pip;
        #pragma unroll
        for (int i = 0; i < 17; i++) {
            const int idx = tid + i * 256;
            CP16(sb + SM_PIH + idx * 16, gp + idx);
        }
        asm volatile("cp.async.commit_group;" ::: "memory");
    }

    // ---- load x (4 threads/token); stage A hi/lo (raw x); partial SS ----
    {
        const int r = tid >> 2, q = tid & 3;
        const float4* xr = (const float4*)(x + (size_t)(tok0 + r) * 128 + q * 32);
        float ss = 0.f;
        #pragma unroll
        for (int e2 = 0; e2 < 4; e2++) {
            float4 a = xr[2 * e2], b = xr[2 * e2 + 1];
            ss += a.x * a.x + a.y * a.y + a.z * a.z + a.w * a.w;
            ss += b.x * b.x + b.y * b.y + b.z * b.z + b.w * b.w;
            uint4 hi, lo;
            pack8(a, b, hi, lo);
            char* p = sm + SM_AH + r * RSB + csw(4 * q + e2) * 16;
            *(uint4*)p = hi;
            *(uint4*)(p + (SM_AL - SM_AH)) = lo;
        }
        s_part[tid] = ss;
    }
    if (tid < 16) {
        s_csdh[tid] = g_csdh[tid];
        if (tid < 15) s_mid[tid] = g_mid[tid];
    }
    asm volatile("cp.async.wait_group 0;" ::: "memory");
    __syncthreads();

    // ---- norms (warps 0-1; other warps proceed into fwd chain) ----
    if (tid < 64) {
        float s = s_part[4 * tid] + s_part[4 * tid + 1]
                + s_part[4 * tid + 2] + s_part[4 * tid + 3];
        float n = __fsqrt_rn(s);
        float cn = fmaxf(n, 1e-8f);
        s_scale[tid] = __fdiv_rn(SQRTD_F, cn);
        s_nh[tid] = __half2float(__float2half_rn(n));
    }

    // per-thread LDSM lane geometry
    const int lrow = (lane & 7) + ((lane >> 3) & 1) * 8;
    const int lq = lane >> 4;
    const u32 aAh0 = sb + SM_AH + (u32)(mrow0 + lrow) * RSB;
    const u32 aAh1 = aAh0 + 16 * RSB;
    const u32 aAl0 = aAh0 + (SM_AL - SM_AH);
    const u32 aAl1 = aAh1 + (SM_AL - SM_AH);
    const u32 aBh0 = sb + SM_PIH + (u32)(ncol0 + lrow) * RSB;
    const u32 aBh1 = aBh0 + 16 * RSB;
    const u32 aBl0 = aBh0 + (SM_PIL - SM_PIH);
    const u32 aBl1 = aBh1 + (SM_PIL - SM_PIH);

    float acc[2][4][4];
    #pragma unroll
    for (int i = 0; i < 2; i++)
        #pragma unroll
        for (int j = 0; j < 4; j++)
            #pragma unroll
            for (int k = 0; k < 4; k++) acc[i][j][k] = 0.f;

    // ---- forward: y_raw = x @ Pi^T (3-product hi/lo fp16) ----
    #pragma unroll 1
    for (int ks = 0; ks < 8; ks++) {
        const u32 co = (u32)(((2 * ks) ^ (ks & 4)) + lq) * 16;
        u32 bh0[4], bh1[4], bl0[4], bl1[4], ah0[4], ah1[4], al0[4], al1[4];
        LDSM_X4(bh0, aBh0 + co);
        LDSM_X4(bh1, aBh1 + co);
        LDSM_X4(bl0, aBl0 + co);
        LDSM_X4(bl1, aBl1 + co);
        LDSM_X4(ah0, aAh0 + co);
        LDSM_X4(ah1, aAh1 + co);
        LDSM_X4(al0, aAl0 + co);
        LDSM_X4(al1, aAl1 + co);
        u32 bh[4][2] = {{bh0[0],bh0[2]},{bh0[1],bh0[3]},{bh1[0],bh1[2]},{bh1[1],bh1[3]}};
        u32 bl[4][2] = {{bl0[0],bl0[2]},{bl0[1],bl0[3]},{bl1[0],bl1[2]},{bl1[1],bl1[3]}};
        #pragma unroll
        for (int nt = 0; nt < 4; nt++) {
            mma16(acc[0][nt], ah0[0], ah0[1], ah0[2], ah0[3], bh[nt][0], bh[nt][1]);
            mma16(acc[1][nt], ah1[0], ah1[1], ah1[2], ah1[3], bh[nt][0], bh[nt][1]);
        }
        #pragma unroll
        for (int nt = 0; nt < 4; nt++) {
            mma16(acc[0][nt], ah0[0], ah0[1], ah0[2], ah0[3], bl[nt][0], bl[nt][1]);
            mma16(acc[1][nt], ah1[0], ah1[1], ah1[2], ah1[3], bl[nt][0], bl[nt][1]);
        }
        #pragma unroll
        for (int nt = 0; nt < 4; nt++) {
            mma16(acc[0][nt], al0[0], al0[1], al0[2], al0[3], bh[nt][0], bh[nt][1]);
            mma16(acc[1][nt], al1[0], al1[1], al1[2], al1[3], bh[nt][0], bh[nt][1]);
        }
    }
    __syncthreads();

    // ---- quantize: y = y_raw*(sqrt_d/norm); binary-search idx; write u32 pairs ----
    {
        float mids[15];
        #pragma unroll
        for (int l = 0; l < 15; l++) mids[l] = s_mid[l];
        u32* aW = (u32*)(sm + SM_AH);
        #pragma unroll
        for (int mt = 0; mt < 2; mt++) {
            const int row0 = mrow0 + mt * 16 + g;
            const float sc0 = s_scale[row0];
            const float sc1 = s_scale[row0 + 8];
            #pragma unroll
            for (int nt = 0; nt < 4; nt++) {
                const int p = (ncol0 >> 1) + nt * 4 + t;
                const int woff = csw(p >> 2) * 4 + (p & 3);
                {
                    int i0 = quant_idx(acc[mt][nt][0] * sc0, mids);
                    int i1 = quant_idx(acc[mt][nt][1] * sc0, mids);
                    aW[row0 * 68 + woff] = hpack(s_csdh[i0], s_csdh[i1]);
                }
                {
                    int i0 = quant_idx(acc[mt][nt][2] * sc1, mids);
                    int i1 = quant_idx(acc[mt][nt][3] * sc1, mids);
                    aW[(row0 + 8) * 68 + woff] = hpack(s_csdh[i0], s_csdh[i1]);
                }
                acc[mt][nt][0] = 0.f; acc[mt][nt][1] = 0.f;
                acc[mt][nt][2] = 0.f; acc[mt][nt][3] = 0.f;
            }
        }
    }
    __syncthreads();

    // ---- backward: z = a_hat @ Pi (1-product: a_hi * Pi_hi via ldmatrix.trans) ----
    {
        const int cnq = (ncol0 >> 3) + lq;
        const u32 cb0 = (u32)csw(cnq) * 16;
        const u32 cb1 = (u32)csw(cnq + 2) * 16;
        const u32 tbase = sb + SM_PIH + (u32)lrow * RSB;
        #pragma unroll 1
        for (int ks = 0; ks < 8; ks++) {
            const u32 rb = tbase + (u32)(16 * ks) * RSB;
            const u32 co = (u32)(((2 * ks) ^ (ks & 4)) + lq) * 16;
            u32 th0[4], th1[4], ah0[4], ah1[4];
            LDSM_X4T(th0, rb + cb0);
            LDSM_X4T(th1, rb + cb1);
            LDSM_X4(ah0, aAh0 + co);
            LDSM_X4(ah1, aAh1 + co);
            u32 bh[4][2] = {{th0[0],th0[1]},{th0[2],th0[3]},{th1[0],th1[1]},{th1[2],th1[3]}};
            #pragma unroll
            for (int nt = 0; nt < 4; nt++) {
                mma16(acc[0][nt], ah0[0], ah0[1], ah0[2], ah0[3], bh[nt][0], bh[nt][1]);
                mma16(acc[1][nt], ah1[0], ah1[1], ah1[2], ah1[3], bh[nt][0], bh[nt][1]);
            }
        }
    }

    // ---- epilogue: scale by fp16-roundtripped norm, store float2 ----
    #pragma unroll
    for (int mt = 0; mt < 2; mt++) {
        #pragma unroll
        for (int nt = 0; nt < 4; nt++) {
            int row0 = mrow0 + mt * 16 + g;
            int col  = ncol0 + nt * 8 + 2 * t;
            float nh0 = s_nh[row0];
            float nh1 = s_nh[row0 + 8];
            *(float2*)(out + (size_t)(tok0 + row0) * 128 + col) =
                make_float2(acc[mt][nt][0] * nh0, acc[mt][nt][1] * nh0);
            *(float2*)(out + (size_t)(tok0 + row0 + 8) * 128 + col) =
                make_float2(acc[mt][nt][2] * nh1, acc[mt][nt][3] * nh1);
        }
    }
}

extern "C" void kernel_launch(void* const* d_in, const int* in_sizes, int n_in,
                              void* d_out, int out_size) {
    const float* x   = (const float*)d_in[0];
    const float* Pi  = (const float*)d_in[1];
    const float* cbk = (const float*)d_in[2];
    float* out = (float*)d_out;

    int ntok = in_sizes[0] / 128;
    int blocks = ntok / 64;

    cudaFuncSetAttribute(tq_fused, cudaFuncAttributeMaxDynamicSharedMemorySize, SMEM_BYTES);
    tq_setup<<<8, 256>>>(Pi, cbk);
    tq_fused<<<blocks, 256, SMEM_BYTES>>>(x, out);
}

// round 15
// speedup vs baseline: 2.1468x; 1.0939x over previous
#include <cuda_runtime.h>
#include <cuda_fp16.h>
#include <cstdint>

typedef uint32_t u32;

#define SQRTD_F 11.313708498984761f
#define RSB 272            // row stride bytes (17 x 16B chunks)

// smem byte offsets
#define SM_PIH  0          // Pi hi : 128*272 = 34816
#define SM_PIL  34816      // Pi lo
#define SM_AH   69632      // A hi : 64*272 = 17408
#define SM_AL   87040      // A lo
#define SM_MISC 104448
#define SMEM_BYTES 107520

// precomputed packed Pi (hi tile then lo tile, smem-identical layout) + tables
__device__ uint4  g_pip[4352];
__device__ u32    g_csd2[256];    // (csd[lo nibble], csd[hi nibble]) fp16 pair
__device__ float  g_mid[15];

static __device__ __forceinline__ u32 smem_u32(const void* p) {
    u32 r;
    asm("{ .reg .u64 t; cvta.to.shared.u64 t, %1; cvt.u32.u64 %0, t; }" : "=r"(r) : "l"(p));
    return r;
}
static __device__ __forceinline__ u32 hpack(__half a, __half b) {
    return (u32)__half_as_ushort(a) | ((u32)__half_as_ushort(b) << 16);
}
static __device__ __forceinline__ int csw(int c) { return c ^ ((c & 8) >> 1); }

static __device__ __forceinline__ void mma16(float c[4], u32 a0, u32 a1, u32 a2, u32 a3,
                                             u32 b0, u32 b1) {
    asm volatile(
        "mma.sync.aligned.m16n8k16.row.col.f32.f16.f16.f32 "
        "{%0,%1,%2,%3},{%4,%5,%6,%7},{%8,%9},{%0,%1,%2,%3};"
        : "+f"(c[0]), "+f"(c[1]), "+f"(c[2]), "+f"(c[3])
        : "r"(a0), "r"(a1), "r"(a2), "r"(a3), "r"(b0), "r"(b1));
}
#define LDSM_X4(r, a) \
    asm volatile("ldmatrix.sync.aligned.m8n8.x4.shared.b16 {%0,%1,%2,%3}, [%4];" \
        : "=r"((r)[0]), "=r"((r)[1]), "=r"((r)[2]), "=r"((r)[3]) : "r"(a))
#define LDSM_X4T(r, a) \
    asm volatile("ldmatrix.sync.aligned.m8n8.x4.trans.shared.b16 {%0,%1,%2,%3}, [%4];" \
        : "=r"((r)[0]), "=r"((r)[1]), "=r"((r)[2]), "=r"((r)[3]) : "r"(a))
#define CP16(s, g) \
    asm volatile("cp.async.cg.shared.global [%0], [%1], 16;" :: "r"(s), "l"(g))

// exact binary-search quantizer: idx = #{l : y > mid[l]} for sorted mids
static __device__ __forceinline__ int quant_idx(float y, const float* m) {
    bool b3 = y > m[7];
    float mA = b3 ? m[11] : m[3];
    bool b2 = y > mA;
    float mB = b3 ? (b2 ? m[13] : m[9]) : (b2 ? m[5] : m[1]);
    bool b1 = y > mB;
    float mC = b3 ? (b2 ? (b1 ? m[14] : m[12]) : (b1 ? m[10] : m[8]))
                  : (b2 ? (b1 ? m[6]  : m[4])  : (b1 ? m[2]  : m[0]));
    bool b0 = y > mC;
    return (((int)b3) << 3) | (((int)b2) << 2) | (((int)b1) << 1) | (int)b0;
}

// pack 8 floats into hi/lo uint4
static __device__ __forceinline__ void pack8(const float4 a, const float4 b,
                                             uint4& hi, uint4& lo) {
    __half h0 = __float2half_rn(a.x), h1 = __float2half_rn(a.y);
    __half h2 = __float2half_rn(a.z), h3 = __float2half_rn(a.w);
    __half h4 = __float2half_rn(b.x), h5 = __float2half_rn(b.y);
    __half h6 = __float2half_rn(b.z), h7 = __float2half_rn(b.w);
    hi.x = hpack(h0, h1); hi.y = hpack(h2, h3);
    hi.z = hpack(h4, h5); hi.w = hpack(h6, h7);
    lo.x = hpack(__float2half_rn(a.x - __half2float(h0)),
                 __float2half_rn(a.y - __half2float(h1)));
    lo.y = hpack(__float2half_rn(a.z - __half2float(h2)),
                 __float2half_rn(a.w - __half2float(h3)));
    lo.z = hpack(__float2half_rn(b.x - __half2float(h4)),
                 __float2half_rn(b.y - __half2float(h5)));
    lo.w = hpack(__float2half_rn(b.z - __half2float(h6)),
                 __float2half_rn(b.w - __half2float(h7)));
}

// ---------------- setup kernel: pack Pi + tables once per launch ----------------
__global__ __launch_bounds__(256)
void tq_setup(const float* __restrict__ Pi, const float* __restrict__ cbk) {
    const int tid = threadIdx.x;
    const int r = blockIdx.x * 16 + (tid >> 4);
    const int c = tid & 15;
    const float4* pp = (const float4*)(Pi + r * 128 + c * 8);
    uint4 hi, lo;
    pack8(pp[0], pp[1], hi, lo);
    g_pip[r * 17 + csw(c)] = hi;
    g_pip[2176 + r * 17 + csw(c)] = lo;
    if (c == 0) {
        uint4 z = make_uint4(0, 0, 0, 0);
        g_pip[r * 17 + 16] = z;
        g_pip[2176 + r * 17 + 16] = z;
    }
    if (blockIdx.x == 0) {
        // paired codebook table: entry j = (csd[j&15], csd[j>>4]) as fp16x2
        int i0 = tid & 15, i1 = tid >> 4;
        __half c0 = __float2half_rn(__fdiv_rn(cbk[i0], SQRTD_F));
        __half c1 = __float2half_rn(__fdiv_rn(cbk[i1], SQRTD_F));
        g_csd2[tid] = hpack(c0, c1);
        if (tid < 15) g_mid[tid] = (cbk[tid] + cbk[tid + 1]) * 0.5f;
    }
}

// ---------------- main kernel ----------------
__global__ __launch_bounds__(256, 2)
void tq_fused(const float* __restrict__ x, float* __restrict__ out) {
    extern __shared__ char sm[];
    u32*    s_csd2  = (u32*)(sm + SM_MISC);             // 256 u32 = 1024 B
    float*  s_mid   = (float*)(sm + SM_MISC + 1024);    // 15 f32
    float*  s_part  = (float*)(sm + SM_MISC + 1152);    // 256 f32
    float*  s_scale = (float*)(sm + SM_MISC + 2176);    // 64 f32
    float*  s_nh    = (float*)(sm + SM_MISC + 2432);    // 64 f32

    const int tid = threadIdx.x;
    const int wid = tid >> 5, lane = tid & 31;
    const int g = lane >> 2, t = lane & 3;
    const int mrow0 = (wid >> 2) * 32;
    const int ncol0 = (wid & 3) * 32;
    const int tok0 = blockIdx.x << 6;

    const u32 sb = smem_u32(sm);

    // ---- copy packed Pi tiles (hi+lo) via cp.async, 17 x 16B per thread ----
    {
        const uint4* gp = g_pip;
        #pragma unroll
        for (int i = 0; i < 17; i++) {
            const int idx = tid + i * 256;
            CP16(sb + SM_PIH + idx * 16, gp + idx);
        }
        asm volatile("cp.async.commit_group;" ::: "memory");
    }

    // ---- load x (4 threads/token); stage A hi/lo (raw x); partial SS ----
    {
        const int r = tid >> 2, q = tid & 3;
        const float4* xr = (const float4*)(x + (size_t)(tok0 + r) * 128 + q * 32);
        float ss = 0.f;
        #pragma unroll
        for (int e2 = 0; e2 < 4; e2++) {
            float4 a = xr[2 * e2], b = xr[2 * e2 + 1];
            ss += a.x * a.x + a.y * a.y + a.z * a.z + a.w * a.w;
            ss += b.x * b.x + b.y * b.y + b.z * b.z + b.w * b.w;
            uint4 hi, lo;
            pack8(a, b, hi, lo);
            char* p = sm + SM_AH + r * RSB + csw(4 * q + e2) * 16;
            *(uint4*)p = hi;
            *(uint4*)(p + (SM_AL - SM_AH)) = lo;
        }
        s_part[tid] = ss;
    }
    s_csd2[tid] = g_csd2[tid];
    if (tid < 15) s_mid[tid] = g_mid[tid];
    asm volatile("cp.async.wait_group 0;" ::: "memory");
    __syncthreads();

    // ---- norms (warps 0-1; other warps proceed into fwd chain) ----
    if (tid < 64) {
        float s = s_part[4 * tid] + s_part[4 * tid + 1]
                + s_part[4 * tid + 2] + s_part[4 * tid + 3];
        float n = __fsqrt_rn(s);
        float cn = fmaxf(n, 1e-8f);
        s_scale[tid] = __fdiv_rn(SQRTD_F, cn);
        s_nh[tid] = __half2float(__float2half_rn(n));
    }

    // per-thread LDSM lane geometry
    const int lrow = (lane & 7) + ((lane >> 3) & 1) * 8;
    const int lq = lane >> 4;
    const u32 aAh0 = sb + SM_AH + (u32)(mrow0 + lrow) * RSB;
    const u32 aAh1 = aAh0 + 16 * RSB;
    const u32 aAl0 = aAh0 + (SM_AL - SM_AH);
    const u32 aAl1 = aAh1 + (SM_AL - SM_AH);
    const u32 aBh0 = sb + SM_PIH + (u32)(ncol0 + lrow) * RSB;
    const u32 aBh1 = aBh0 + 16 * RSB;
    const u32 aBl0 = aBh0 + (SM_PIL - SM_PIH);
    const u32 aBl1 = aBh1 + (SM_PIL - SM_PIH);

    float acc[2][4][4];
    #pragma unroll
    for (int i = 0; i < 2; i++)
        #pragma unroll
        for (int j = 0; j < 4; j++)
            #pragma unroll
            for (int k = 0; k < 4; k++) acc[i][j][k] = 0.f;

    // ---- forward: y_raw = x @ Pi^T (3-product hi/lo fp16), FULLY UNROLLED ----
    #pragma unroll
    for (int ks = 0; ks < 8; ks++) {
        const u32 co = (u32)(((2 * ks) ^ (ks & 4)) + lq) * 16;
        u32 bh0[4], bh1[4], bl0[4], bl1[4], ah0[4], ah1[4], al0[4], al1[4];
        LDSM_X4(bh0, aBh0 + co);
        LDSM_X4(bh1, aBh1 + co);
        LDSM_X4(bl0, aBl0 + co);
        LDSM_X4(bl1, aBl1 + co);
        LDSM_X4(ah0, aAh0 + co);
        LDSM_X4(ah1, aAh1 + co);
        LDSM_X4(al0, aAl0 + co);
        LDSM_X4(al1, aAl1 + co);
        u32 bh[4][2] = {{bh0[0],bh0[2]},{bh0[1],bh0[3]},{bh1[0],bh1[2]},{bh1[1],bh1[3]}};
        u32 bl[4][2] = {{bl0[0],bl0[2]},{bl0[1],bl0[3]},{bl1[0],bl1[2]},{bl1[1],bl1[3]}};
        #pragma unroll
        for (int nt = 0; nt < 4; nt++) {
            mma16(acc[0][nt], ah0[0], ah0[1], ah0[2], ah0[3], bh[nt][0], bh[nt][1]);
            mma16(acc[1][nt], ah1[0], ah1[1], ah1[2], ah1[3], bh[nt][0], bh[nt][1]);
        }
        #pragma unroll
        for (int nt = 0; nt < 4; nt++) {
            mma16(acc[0][nt], ah0[0], ah0[1], ah0[2], ah0[3], bl[nt][0], bl[nt][1]);
            mma16(acc[1][nt], ah1[0], ah1[1], ah1[2], ah1[3], bl[nt][0], bl[nt][1]);
        }
        #pragma unroll
        for (int nt = 0; nt < 4; nt++) {
            mma16(acc[0][nt], al0[0], al0[1], al0[2], al0[3], bh[nt][0], bh[nt][1]);
            mma16(acc[1][nt], al1[0], al1[1], al1[2], al1[3], bh[nt][0], bh[nt][1]);
        }
    }
    __syncthreads();

    // ---- quantize: y = y_raw*(sqrt_d/norm); paired-table lookup; write u32 ----
    {
        float mids[15];
        #pragma unroll
        for (int l = 0; l < 15; l++) mids[l] = s_mid[l];
        u32* aW = (u32*)(sm + SM_AH);
        #pragma unroll
        for (int mt = 0; mt < 2; mt++) {
            const int row0 = mrow0 + mt * 16 + g;
            const float sc0 = s_scale[row0];
            const float sc1 = s_scale[row0 + 8];
            #pragma unroll
            for (int nt = 0; nt < 4; nt++) {
                const int p = (ncol0 >> 1) + nt * 4 + t;
                const int woff = csw(p >> 2) * 4 + (p & 3);
                {
                    int i0 = quant_idx(acc[mt][nt][0] * sc0, mids);
                    int i1 = quant_idx(acc[mt][nt][1] * sc0, mids);
                    aW[row0 * 68 + woff] = s_csd2[i0 | (i1 << 4)];
                }
                {
                    int i0 = quant_idx(acc[mt][nt][2] * sc1, mids);
                    int i1 = quant_idx(acc[mt][nt][3] * sc1, mids);
                    aW[(row0 + 8) * 68 + woff] = s_csd2[i0 | (i1 << 4)];
                }
                acc[mt][nt][0] = 0.f; acc[mt][nt][1] = 0.f;
                acc[mt][nt][2] = 0.f; acc[mt][nt][3] = 0.f;
            }
        }
    }
    __syncthreads();

    // ---- backward: z = a_hat @ Pi (a_hi * Pi_hi via ldmatrix.trans), UNROLLED ----
    {
        const int cnq = (ncol0 >> 3) + lq;
        const u32 cb0 = (u32)csw(cnq) * 16;
        const u32 cb1 = (u32)csw(cnq + 2) * 16;
        const u32 tbase = sb + SM_PIH + (u32)lrow * RSB;
        #pragma unroll
        for (int ks = 0; ks < 8; ks++) {
            const u32 rb = tbase + (u32)(16 * ks) * RSB;
            const u32 co = (u32)(((2 * ks) ^ (ks & 4)) + lq) * 16;
            u32 th0[4], th1[4], ah0[4], ah1[4];
            LDSM_X4T(th0, rb + cb0);
            LDSM_X4T(th1, rb + cb1);
            LDSM_X4(ah0, aAh0 + co);
            LDSM_X4(ah1, aAh1 + co);
            u32 bh[4][2] = {{th0[0],th0[1]},{th0[2],th0[3]},{th1[0],th1[1]},{th1[2],th1[3]}};
            #pragma unroll
            for (int nt = 0; nt < 4; nt++) {
                mma16(acc[0][nt], ah0[0], ah0[1], ah0[2], ah0[3], bh[nt][0], bh[nt][1]);
                mma16(acc[1][nt], ah1[0], ah1[1], ah1[2], ah1[3], bh[nt][0], bh[nt][1]);
            }
        }
    }

    // ---- epilogue: scale by fp16-roundtripped norm, store float2 ----
    #pragma unroll
    for (int mt = 0; mt < 2; mt++) {
        #pragma unroll
        for (int nt = 0; nt < 4; nt++) {
            int row0 = mrow0 + mt * 16 + g;
            int col  = ncol0 + nt * 8 + 2 * t;
            float nh0 = s_nh[row0];
            float nh1 = s_nh[row0 + 8];
            *(float2*)(out + (size_t)(tok0 + row0) * 128 + col) =
                make_float2(acc[mt][nt][0] * nh0, acc[mt][nt][1] * nh0);
            *(float2*)(out + (size_t)(tok0 + row0 + 8) * 128 + col) =
                make_float2(acc[mt][nt][2] * nh1, acc[mt][nt][3] * nh1);
        }
    }
}

extern "C" void kernel_launch(void* const* d_in, const int* in_sizes, int n_in,
                              void* d_out, int out_size) {
    const float* x   = (const float*)d_in[0];
    const float* Pi  = (const float*)d_in[1];
    const float* cbk = (const float*)d_in[2];
    float* out = (float*)d_out;

    int ntok = in_sizes[0] / 128;
    int blocks = ntok / 64;

    cudaFuncSetAttribute(tq_fused, cudaFuncAttributeMaxDynamicSharedMemorySize, SMEM_BYTES);
    tq_setup<<<8, 256>>>(Pi, cbk);
    tq_fused<<<blocks, 256, SMEM_BYTES>>>(x, out);
}